// round 1
// baseline (speedup 1.0000x reference)
#include <cuda_runtime.h>
#include <cstdint>
#include <cstdio>

#define NN 50000
#define EE 500000

// ---------------- scratch (static device globals; no runtime allocation) ----------------
__device__ __align__(16) float g_A[(size_t)NN * 1280];   // concat [m0,m1,m2,m3,h] rows (also pooling scratch)
__device__ __align__(16) float g_B[1280 * 256];          // stacked weights [Wl0..Wl3; sum(Wr)]
__device__ __align__(16) float g_bias[256];              // sum_t bl[t]
__device__ __align__(16) float g_h[(size_t)NN * 256];
__device__ __align__(16) float g_h2[(size_t)NN * 256];
__device__ __align__(16) float g_cnt[4 * NN];            // per-relation in-degree (as float)
__device__ __align__(16) float g_stats[128];             // batchnorm sum / sumsq

// ---------------- utility kernels ----------------
__global__ void zero_buf(float* __restrict__ p, long n) {
    long i = (long)blockIdx.x * blockDim.x + threadIdx.x;
    if (i < n) p[i] = 0.0f;
}

__global__ void count_k(const int* __restrict__ edge, float* __restrict__ cnt) {
    int e = blockIdx.x * blockDim.x + threadIdx.x;
    if (e < EE) atomicAdd(&cnt[edge[EE + e]], 1.0f);
}

// Build stacked B = [Wl[0];Wl[1];Wl[2];Wl[3]; sum_t Wr[t]]  (K = 5*Din rows x 256 cols)
__global__ void build_B(const float* __restrict__ Wl, const float* __restrict__ Wr,
                        const float* __restrict__ bl, int Din) {
    long i = (long)blockIdx.x * blockDim.x + threadIdx.x;
    long total = (long)5 * Din * 256;
    if (i >= total) return;
    int k = (int)(i / 256), n = (int)(i % 256);
    float v;
    if (k < 4 * Din) {
        int t = k / Din, kk = k - t * Din;
        v = Wl[((size_t)t * Din + kk) * 256 + n];
    } else {
        int kk = k - 4 * Din;
        v = Wr[(size_t)kk * 256 + n] + Wr[((size_t)Din + kk) * 256 + n] +
            Wr[((size_t)2 * Din + kk) * 256 + n] + Wr[((size_t)3 * Din + kk) * 256 + n];
    }
    g_B[i] = v;
    if (i < 256) g_bias[i] = bl[i] + bl[256 + i] + bl[512 + i] + bl[768 + i];
}

// Zero the m-part of A and copy h into the last Din columns. Row length = 5*D floats.
template <int D>
__global__ void prep_A(const float* __restrict__ h) {
    const long R4 = 5 * D / 4;  // float4 per row
    long idx = (long)blockIdx.x * blockDim.x + threadIdx.x;
    if (idx >= (long)NN * R4) return;
    long row = idx / R4;
    int c4 = (int)(idx % R4);
    float4 v = make_float4(0.f, 0.f, 0.f, 0.f);
    if (c4 >= D) v = *(const float4*)&h[(size_t)row * D + (size_t)(c4 - D) * 4];
    *(float4*)&g_A[(size_t)row * 5 * D + (size_t)c4 * 4] = v;
}

// Scatter-add h[src] into out[dst] with vector global reductions.
template <int D4>
__global__ void scatter_k(const int* __restrict__ edge, const float* __restrict__ h,
                          float* __restrict__ out, int ostride, int coff) {
    long idx = (long)blockIdx.x * blockDim.x + threadIdx.x;
    if (idx >= (long)EE * D4) return;
    int e = (int)(idx / D4);
    int j = (int)(idx % D4);
    int s = edge[e];
    int d = edge[EE + e];
    float4 v = *(const float4*)&h[(size_t)s * (D4 * 4) + (size_t)j * 4];
    float* p = &out[(size_t)d * ostride + coff + (size_t)j * 4];
    asm volatile("red.global.add.v4.f32 [%0], {%1,%2,%3,%4};"
                 :: "l"(p), "f"(v.x), "f"(v.y), "f"(v.z), "f"(v.w) : "memory");
}

// Divide the m-part of A by max(count, 1)
template <int D>
__global__ void scale_m() {
    long idx = (long)blockIdx.x * blockDim.x + threadIdx.x;  // float4 index over m-part
    if (idx >= (long)NN * D) return;                         // 4D floats = D float4 per row
    int row = (int)(idx / D);
    int c4 = (int)(idx % D);
    int t = c4 / (D / 4);
    float inv = 1.0f / fmaxf(g_cnt[(size_t)t * NN + row], 1.0f);
    float4* p = (float4*)&g_A[(size_t)row * 5 * D + (size_t)c4 * 4];
    float4 v = *p;
    v.x *= inv; v.y *= inv; v.z *= inv; v.w *= inv;
    *p = v;
}

// ---------------- SGEMM: C[M,Nn] = A[M,K](lda) @ B[K,Nn] (+bias)(+relu) ----------------
template <int BN, bool RELU, bool BIAS>
__global__ void __launch_bounds__((128 / 8) * (BN / 8))
sgemm_k(const float* __restrict__ A, int lda, const float* __restrict__ B,
        const float* __restrict__ bias, float* __restrict__ C, int M, int Nn, int K) {
    const int BM = 128, BK = 16, TM = 8, TN = 8;
    const int THREADS = (BM / TM) * (BN / TN);
    __shared__ float As[BK][BM];
    __shared__ float Bs[BK][BN];
    int tid = threadIdx.x;
    int rowC = blockIdx.y * BM, colC = blockIdx.x * BN;
    int tx = tid % (BN / TN);
    int ty = tid / (BN / TN);

    const int A_LOADS = (BM * BK / 4) / THREADS;
    const int B_LOADS = (BK * BN / 4) / THREADS;
    int aRow = tid / (BK / 4);
    int aCol4 = tid % (BK / 4);
    int bRow = tid / (BN / 4);
    int bCol4 = tid % (BN / 4);
    const int A_ROW_STRIDE = THREADS / (BK / 4);
    const int B_ROW_STRIDE = THREADS / (BN / 4);

    float acc[TM][TN] = {};

    for (int k0 = 0; k0 < K; k0 += BK) {
#pragma unroll
        for (int i = 0; i < A_LOADS; i++) {
            int r = aRow + i * A_ROW_STRIDE;
            int grow = rowC + r;
            float4 v = make_float4(0.f, 0.f, 0.f, 0.f);
            if (grow < M) v = *(const float4*)&A[(size_t)grow * lda + k0 + aCol4 * 4];
            As[aCol4 * 4 + 0][r] = v.x;
            As[aCol4 * 4 + 1][r] = v.y;
            As[aCol4 * 4 + 2][r] = v.z;
            As[aCol4 * 4 + 3][r] = v.w;
        }
#pragma unroll
        for (int i = 0; i < B_LOADS; i++) {
            int r = bRow + i * B_ROW_STRIDE;
            *(float4*)&Bs[r][bCol4 * 4] =
                *(const float4*)&B[(size_t)(k0 + r) * Nn + colC + bCol4 * 4];
        }
        __syncthreads();
#pragma unroll
        for (int k = 0; k < BK; k++) {
            float4 a0 = *(const float4*)&As[k][ty * TM];
            float4 a1 = *(const float4*)&As[k][ty * TM + 4];
            float4 b0 = *(const float4*)&Bs[k][tx * TN];
            float4 b1 = *(const float4*)&Bs[k][tx * TN + 4];
            float ar[TM] = {a0.x, a0.y, a0.z, a0.w, a1.x, a1.y, a1.z, a1.w};
            float br[TN] = {b0.x, b0.y, b0.z, b0.w, b1.x, b1.y, b1.z, b1.w};
#pragma unroll
            for (int i = 0; i < TM; i++)
#pragma unroll
                for (int j = 0; j < TN; j++) acc[i][j] += ar[i] * br[j];
        }
        __syncthreads();
    }

#pragma unroll
    for (int i = 0; i < TM; i++) {
        int grow = rowC + ty * TM + i;
        if (grow >= M) continue;
#pragma unroll
        for (int j = 0; j < TN; j += 4) {
            int gcol = colC + tx * TN + j;
            float4 v = make_float4(acc[i][j], acc[i][j + 1], acc[i][j + 2], acc[i][j + 3]);
            if (BIAS) {
                v.x += bias[gcol]; v.y += bias[gcol + 1];
                v.z += bias[gcol + 2]; v.w += bias[gcol + 3];
            }
            if (RELU) {
                v.x = fmaxf(v.x, 0.f); v.y = fmaxf(v.y, 0.f);
                v.z = fmaxf(v.z, 0.f); v.w = fmaxf(v.w, 0.f);
            }
            *(float4*)&C[(size_t)grow * Nn + gcol] = v;
        }
    }
}

// ---------------- tail kernels ----------------
// h = (h + s) / max(cnt,1)  over N x 128
__global__ void pool_combine(float* __restrict__ h, const float* __restrict__ s,
                             const float* __restrict__ cnt) {
    long idx = (long)blockIdx.x * blockDim.x + threadIdx.x;  // float4 index
    if (idx >= (long)NN * 32) return;
    int row = (int)(idx >> 5);
    float inv = 1.0f / fmaxf(cnt[row], 1.0f);
    float4 a = *(float4*)&h[idx * 4];
    float4 b = *(const float4*)&s[idx * 4];
    a.x = (a.x + b.x) * inv; a.y = (a.y + b.y) * inv;
    a.z = (a.z + b.z) * inv; a.w = (a.w + b.w) * inv;
    *(float4*)&h[idx * 4] = a;
}

// LayerNorm over last dim = 128. One warp per row.
__global__ void layernorm_k(const float* __restrict__ in, float* __restrict__ out,
                            const float* __restrict__ g, const float* __restrict__ b) {
    int row = blockIdx.x * 8 + (threadIdx.x >> 5);
    int lane = threadIdx.x & 31;
    if (row >= NN) return;
    float4 v = *(const float4*)&in[(size_t)row * 128 + lane * 4];
    float s = v.x + v.y + v.z + v.w;
    float q = v.x * v.x + v.y * v.y + v.z * v.z + v.w * v.w;
#pragma unroll
    for (int o = 16; o; o >>= 1) {
        s += __shfl_xor_sync(0xffffffffu, s, o);
        q += __shfl_xor_sync(0xffffffffu, q, o);
    }
    float mu = s * (1.0f / 128.0f);
    float var = q * (1.0f / 128.0f) - mu * mu;
    float r = rsqrtf(var + 1e-5f);
    float4 gg = *(const float4*)&g[lane * 4];
    float4 bb = *(const float4*)&b[lane * 4];
    float4 o4;
    o4.x = (v.x - mu) * r * gg.x + bb.x;
    o4.y = (v.y - mu) * r * gg.y + bb.y;
    o4.z = (v.z - mu) * r * gg.z + bb.z;
    o4.w = (v.w - mu) * r * gg.w + bb.w;
    *(float4*)&out[(size_t)row * 128 + lane * 4] = o4;
}

// BatchNorm stats over N rows x 64 channels
__global__ void bn_stats(const float* __restrict__ z) {
    __shared__ float ssum[256], ssq[256];
    int c = threadIdx.x & 63;
    int sub = threadIdx.x >> 6;
    float s = 0.f, q = 0.f;
    for (long r = (long)blockIdx.x * 4 + sub; r < NN; r += (long)gridDim.x * 4) {
        float v = z[r * 64 + c];
        s += v; q += v * v;
    }
    ssum[threadIdx.x] = s; ssq[threadIdx.x] = q;
    __syncthreads();
    if (sub == 0) {
        s = ssum[c] + ssum[64 + c] + ssum[128 + c] + ssum[192 + c];
        q = ssq[c] + ssq[64 + c] + ssq[128 + c] + ssq[192 + c];
        atomicAdd(&g_stats[c], s);
        atomicAdd(&g_stats[64 + c], q);
    }
}

// normalize -> GEMV 64x7 -> softmax
__global__ void finalize_k(const float* __restrict__ z, const float* __restrict__ bn_g,
                           const float* __restrict__ bn_b, const float* __restrict__ cW2,
                           const float* __restrict__ cb2, float* __restrict__ out) {
    __shared__ float w[448], smu[64], sr[64], sg[64], sb[64], sb2[7];
    int tid = threadIdx.x;
    for (int i = tid; i < 448; i += blockDim.x) w[i] = cW2[i];
    if (tid < 64) {
        float mu = g_stats[tid] / (float)NN;
        float var = g_stats[64 + tid] / (float)NN - mu * mu;
        smu[tid] = mu;
        sr[tid] = rsqrtf(var + 1e-5f);
        sg[tid] = bn_g[tid];
        sb[tid] = bn_b[tid];
    }
    if (tid < 7) sb2[tid] = cb2[tid];
    __syncthreads();
    int row = blockIdx.x * blockDim.x + tid;
    if (row >= NN) return;
    float logits[7];
#pragma unroll
    for (int j = 0; j < 7; j++) logits[j] = sb2[j];
    for (int c = 0; c < 64; c += 4) {
        float4 v4 = *(const float4*)&z[(size_t)row * 64 + c];
        float vv[4] = {v4.x, v4.y, v4.z, v4.w};
#pragma unroll
        for (int u = 0; u < 4; u++) {
            int cc = c + u;
            float v = (vv[u] - smu[cc]) * sr[cc] * sg[cc] + sb[cc];
#pragma unroll
            for (int j = 0; j < 7; j++) logits[j] += v * w[cc * 7 + j];
        }
    }
    float m = logits[0];
#pragma unroll
    for (int j = 1; j < 7; j++) m = fmaxf(m, logits[j]);
    float ssum = 0.f;
#pragma unroll
    for (int j = 0; j < 7; j++) { logits[j] = expf(logits[j] - m); ssum += logits[j]; }
    float inv = 1.0f / ssum;
#pragma unroll
    for (int j = 0; j < 7; j++) out[(size_t)row * 7 + j] = logits[j] * inv;
}

// ---------------- host launcher ----------------
static inline int cdiv(long a, int b) { return (int)((a + b - 1) / b); }

extern "C" void kernel_launch(void* const* d_in, const int* in_sizes, int n_in,
                              void* d_out, int out_size) {
    const float* x = (const float*)d_in[0];
    const int* edges[4] = {(const int*)d_in[1], (const int*)d_in[2],
                           (const int*)d_in[3], (const int*)d_in[4]};
    const float* Wl0 = (const float*)d_in[5];
    const float* bl0 = (const float*)d_in[6];
    const float* Wr0 = (const float*)d_in[7];
    const float* Wl = (const float*)d_in[8];
    const float* bl = (const float*)d_in[9];
    const float* Wr = (const float*)d_in[10];
    const float* lin_W = (const float*)d_in[11];
    const float* lin_b = (const float*)d_in[12];
    const float* norm_g = (const float*)d_in[13];
    const float* norm_b = (const float*)d_in[14];
    const float* pW1 = (const float*)d_in[15];
    const float* pb1 = (const float*)d_in[16];
    const float* pln_g = (const float*)d_in[17];
    const float* pln_b = (const float*)d_in[18];
    const float* pW2 = (const float*)d_in[19];
    const float* pb2 = (const float*)d_in[20];
    const float* cW1 = (const float*)d_in[21];
    const float* cb1 = (const float*)d_in[22];
    const float* bn_g = (const float*)d_in[23];
    const float* bn_b = (const float*)d_in[24];
    const float* cW2 = (const float*)d_in[25];
    const float* cb2 = (const float*)d_in[26];
    float* out = (float*)d_out;

    float *pA, *pB, *pbias, *ph, *ph2, *pcnt, *pstats;
    cudaGetSymbolAddress((void**)&pA, g_A);
    cudaGetSymbolAddress((void**)&pB, g_B);
    cudaGetSymbolAddress((void**)&pbias, g_bias);
    cudaGetSymbolAddress((void**)&ph, g_h);
    cudaGetSymbolAddress((void**)&ph2, g_h2);
    cudaGetSymbolAddress((void**)&pcnt, g_cnt);
    cudaGetSymbolAddress((void**)&pstats, g_stats);

    const int T = 256;

    // in-degree counts per relation
    zero_buf<<<cdiv(4L * NN, T), T>>>(pcnt, 4L * NN);
    for (int t = 0; t < 4; t++)
        count_k<<<cdiv(EE, T), T>>>(edges[t], pcnt + (size_t)t * NN);

    // ---- Layer 0 (Din = 128) ----
    build_B<<<cdiv(5L * 128 * 256, T), T>>>(Wl0, Wr0, bl0, 128);
    prep_A<128><<<cdiv((long)NN * 160, T), T>>>(x);
    for (int t = 0; t < 4; t++)
        scatter_k<32><<<cdiv((long)EE * 32, T), T>>>(edges[t], x, pA, 640, t * 128);
    scale_m<128><<<cdiv((long)NN * 128, T), T>>>();
    sgemm_k<128, true, true><<<dim3(2, cdiv(NN, 128)), 256>>>(pA, 640, pB, pbias, ph, NN, 256, 640);

    // ---- Layers 1, 2 (Din = 256) ----
    float* hin = ph;
    float* hout = ph2;
    for (int l = 0; l < 2; l++) {
        build_B<<<cdiv(5L * 256 * 256, T), T>>>(Wl + (size_t)l * 4 * 256 * 256,
                                                Wr + (size_t)l * 4 * 256 * 256,
                                                bl + (size_t)l * 4 * 256, 256);
        prep_A<256><<<cdiv((long)NN * 320, T), T>>>(hin);
        for (int t = 0; t < 4; t++)
            scatter_k<64><<<cdiv((long)EE * 64, T), T>>>(edges[t], hin, pA, 1280, t * 256);
        scale_m<256><<<cdiv((long)NN * 256, T), T>>>();
        sgemm_k<128, true, true><<<dim3(2, cdiv(NN, 128)), 256>>>(pA, 1280, pB, pbias, hout, NN, 256, 1280);
        float* tmp = hin; hin = hout; hout = tmp;
    }
    // GNN output now in hin == ph

    // lin: [N,256] @ [256,128] + b
    sgemm_k<128, false, true><<<dim3(1, cdiv(NN, 128)), 256>>>(hin, 256, lin_W, lin_b, ph2, NN, 128, 256);

    // onset pooling: s = scatter_sum(h[src], dst); h = (h + s)/max(c0,1)
    zero_buf<<<cdiv((long)NN * 128, T), T>>>(pA, (long)NN * 128);
    scatter_k<32><<<cdiv((long)EE * 32, T), T>>>(edges[0], ph2, pA, 128, 0);
    pool_combine<<<cdiv((long)NN * 32, T), T>>>(ph2, pA, pcnt);

    // layernorm
    layernorm_k<<<cdiv(NN, 8), 256>>>(ph2, ph, norm_g, norm_b);
    // pool_mlp
    sgemm_k<128, true, true><<<dim3(1, cdiv(NN, 128)), 256>>>(ph, 128, pW1, pb1, ph2, NN, 128, 128);
    layernorm_k<<<cdiv(NN, 8), 256>>>(ph2, ph, pln_g, pln_b);
    sgemm_k<128, false, true><<<dim3(1, cdiv(NN, 128)), 256>>>(ph, 128, pW2, pb2, ph2, NN, 128, 128);
    // clf first layer + relu
    sgemm_k<64, true, true><<<dim3(1, cdiv(NN, 128)), 128>>>(ph2, 128, cW1, cb1, ph, NN, 64, 128);
    // batchnorm stats + fused finalize
    zero_buf<<<1, 128>>>(pstats, 128);
    bn_stats<<<512, 256>>>(ph);
    finalize_k<<<cdiv(NN, 256), 256>>>(ph, bn_g, bn_b, cW2, cb2, out);
}

// round 3
// speedup vs baseline: 1.2695x; 1.2695x over previous
#include <cuda_runtime.h>
#include <cuda_bf16.h>
#include <cstdint>

#define NN 50000
#define EE 500000

// ---------------- scratch (static device globals; no runtime allocation) ----------------
__device__ __align__(16) float g_m[(size_t)NN * 1024];              // scatter sums (4 relations x D), also pooling scratch
__device__ __align__(16) __nv_bfloat16 g_Abf[(size_t)NN * 2560];    // A' = [hi(5D) | lo(5D)], KA = 10D
__device__ __align__(16) __nv_bfloat16 g_Bbf[(size_t)256 * 3840];   // B' = [Bhi; Blo; Bhi], K3 = 15D, row-major [n][k]
__device__ __align__(16) float g_bias[256];
__device__ __align__(16) float g_h[(size_t)NN * 256];
__device__ __align__(16) float g_h2[(size_t)NN * 256];
__device__ __align__(16) float g_cnt[4 * NN];
__device__ __align__(16) float g_stats[128];

// ---------------- portable async-copy helpers ----------------
__device__ __forceinline__ uint32_t smem_u32(const void* p) {
    uint32_t a;
    asm("{ .reg .u64 t; cvta.to.shared.u64 t, %1; cvt.u32.u64 %0, t; }" : "=r"(a) : "l"(p));
    return a;
}
__device__ __forceinline__ void cp_async16(uint32_t dst, const void* src, int sz) {
    asm volatile("cp.async.cg.shared.global [%0], [%1], 16, %2;"
                 :: "r"(dst), "l"(src), "r"(sz) : "memory");
}
__device__ __forceinline__ void cp_commit() { asm volatile("cp.async.commit_group;" ::: "memory"); }
template <int Nw>
__device__ __forceinline__ void cp_wait() { asm volatile("cp.async.wait_group %0;" ::"n"(Nw) : "memory"); }

// ---------------- bf16 mma.sync GEMM ----------------
// C[M,256] = A'[M,KA] @ B'[256,K3]^T (B row-major [n][k]), bias + relu.
// Split-K chunk mapping: chunk c of B pairs with A chunk (c < NCb ? c : c - NCb).
#define BKC 32

__global__ void __launch_bounds__(256, 2)
mma_gemm(const __nv_bfloat16* __restrict__ A, int KA,
         const __nv_bfloat16* __restrict__ B, int K3,
         const float* __restrict__ bias, float* __restrict__ C,
         int NCb, int NC) {
    __shared__ __nv_bfloat16 As[2][128][40];
    __shared__ __nv_bfloat16 Bs[2][128][40];
    int tid = threadIdx.x;
    int wid = tid >> 5, lane = tid & 31;
    int t4 = lane >> 2, tq = lane & 3;
    int warp_m = wid & 3, warp_n = wid >> 1 >> 2;  // placeholder; fixed below
    warp_n = wid >> 2;                              // 0..1
    int rowBase = blockIdx.x * 128;
    int colC = blockIdx.y * 128;
    int m0 = warp_m * 32, n0 = warp_n * 64;

    float acc[2][8][4];
#pragma unroll
    for (int i = 0; i < 2; i++)
#pragma unroll
        for (int j = 0; j < 8; j++)
#pragma unroll
            for (int q = 0; q < 4; q++) acc[i][j][q] = 0.f;

    // loader mapping: 512 x 16B per tile; 2 per thread
    int lr = tid >> 2;          // 0..63  (row pair base; actual row = u>>2)
    (void)lr;

    auto issue = [&](int c, int s) {
        int ac = (c < NCb) ? c : c - NCb;
#pragma unroll
        for (int i = 0; i < 2; i++) {
            int u = tid + i * 256;
            int r = u >> 2, q = u & 3;
            int gr = rowBase + r;
            const __nv_bfloat16* srcA = A + (size_t)gr * KA + ac * BKC + q * 8;
            cp_async16(smem_u32(&As[s][r][q * 8]), srcA, gr < NN ? 16 : 0);
            const __nv_bfloat16* srcB = B + (size_t)(colC + r) * K3 + c * BKC + q * 8;
            cp_async16(smem_u32(&Bs[s][r][q * 8]), srcB, 16);
        }
        cp_commit();
    };

    issue(0, 0);

    for (int c = 0; c < NC; c++) {
        int s = c & 1;
        if (c + 1 < NC) {
            issue(c + 1, s ^ 1);
            cp_wait<1>();
        } else {
            cp_wait<0>();
        }
        __syncthreads();

        const __nv_bfloat16(*as)[40] = As[s];
        const __nv_bfloat16(*bs)[40] = Bs[s];
#pragma unroll
        for (int ks = 0; ks < 2; ks++) {
            uint32_t a[2][4], b[8][2];
#pragma unroll
            for (int im = 0; im < 2; im++) {
                int rm = m0 + im * 16 + t4;
                int kc = ks * 16 + tq * 2;
                a[im][0] = *(const uint32_t*)&as[rm][kc];
                a[im][1] = *(const uint32_t*)&as[rm + 8][kc];
                a[im][2] = *(const uint32_t*)&as[rm][kc + 8];
                a[im][3] = *(const uint32_t*)&as[rm + 8][kc + 8];
            }
#pragma unroll
            for (int in = 0; in < 8; in++) {
                int rn = n0 + in * 8 + t4;
                int kc = ks * 16 + tq * 2;
                b[in][0] = *(const uint32_t*)&bs[rn][kc];
                b[in][1] = *(const uint32_t*)&bs[rn][kc + 8];
            }
#pragma unroll
            for (int im = 0; im < 2; im++)
#pragma unroll
                for (int in = 0; in < 8; in++) {
                    asm volatile(
                        "mma.sync.aligned.m16n8k16.row.col.f32.bf16.bf16.f32 "
                        "{%0,%1,%2,%3}, {%4,%5,%6,%7}, {%8,%9}, {%0,%1,%2,%3};"
                        : "+f"(acc[im][in][0]), "+f"(acc[im][in][1]),
                          "+f"(acc[im][in][2]), "+f"(acc[im][in][3])
                        : "r"(a[im][0]), "r"(a[im][1]), "r"(a[im][2]), "r"(a[im][3]),
                          "r"(b[in][0]), "r"(b[in][1]));
                }
        }
        __syncthreads();
    }

    // epilogue: bias + relu, direct float2 stores
#pragma unroll
    for (int im = 0; im < 2; im++) {
        int gr0 = rowBase + m0 + im * 16 + t4;
#pragma unroll
        for (int in = 0; in < 8; in++) {
            int col = colC + n0 + in * 8 + tq * 2;
            float bx = bias[col], by = bias[col + 1];
            if (gr0 < NN) {
                float2 v = make_float2(fmaxf(acc[im][in][0] + bx, 0.f),
                                       fmaxf(acc[im][in][1] + by, 0.f));
                *(float2*)&C[(size_t)gr0 * 256 + col] = v;
            }
            if (gr0 + 8 < NN) {
                float2 v = make_float2(fmaxf(acc[im][in][2] + bx, 0.f),
                                       fmaxf(acc[im][in][3] + by, 0.f));
                *(float2*)&C[(size_t)(gr0 + 8) * 256 + col] = v;
            }
        }
    }
}

// ---------------- utility kernels ----------------
__global__ void zero_buf(float* __restrict__ p, long n) {
    long i = (long)blockIdx.x * blockDim.x + threadIdx.x;
    if (i < n) p[i] = 0.0f;
}

__global__ void count_k(const int* __restrict__ edge, float* __restrict__ cnt) {
    int e = blockIdx.x * blockDim.x + threadIdx.x;
    if (e < EE) atomicAdd(&cnt[edge[EE + e]], 1.0f);
}

// Build B' (bf16 hi/lo stacked) + summed bias. Stacked rows: [Wl(4D); sum Wr(D)] -> [hi;lo;hi]
__global__ void build_Bbf(const float* __restrict__ Wl, const float* __restrict__ Wr,
                          const float* __restrict__ bl, int D) {
    long i = (long)blockIdx.x * blockDim.x + threadIdx.x;
    long total = (long)5 * D * 256;
    if (i >= total) return;
    int k = (int)(i / 256), n = (int)(i % 256);
    float v;
    if (k < 4 * D) {
        v = Wl[(size_t)k * 256 + n];
    } else {
        int kk = k - 4 * D;
        v = Wr[(size_t)kk * 256 + n] + Wr[((size_t)D + kk) * 256 + n] +
            Wr[((size_t)2 * D + kk) * 256 + n] + Wr[((size_t)3 * D + kk) * 256 + n];
    }
    int K3 = 15 * D;
    __nv_bfloat16 hi = __float2bfloat16_rn(v);
    __nv_bfloat16 lo = __float2bfloat16_rn(v - __bfloat162float(hi));
    g_Bbf[(size_t)n * K3 + k] = hi;
    g_Bbf[(size_t)n * K3 + 5 * D + k] = lo;
    g_Bbf[(size_t)n * K3 + 10 * D + k] = hi;
    if (i < 256) g_bias[i] = bl[i] + bl[256 + i] + bl[512 + i] + bl[768 + i];
}

// Scatter-add h[src] into out[dst] with vector global reductions.
template <int D4>
__global__ void scatter_k(const int* __restrict__ edge, const float* __restrict__ h,
                          float* __restrict__ out, int ostride, int coff) {
    long idx = (long)blockIdx.x * blockDim.x + threadIdx.x;
    if (idx >= (long)EE * D4) return;
    int e = (int)(idx / D4);
    int j = (int)(idx % D4);
    int s = edge[e];
    int d = edge[EE + e];
    float4 v = *(const float4*)&h[(size_t)s * (D4 * 4) + (size_t)j * 4];
    float* p = &out[(size_t)d * ostride + coff + (size_t)j * 4];
    asm volatile("red.global.add.v4.f32 [%0], {%1,%2,%3,%4};"
                 :: "l"(p), "f"(v.x), "f"(v.y), "f"(v.z), "f"(v.w) : "memory");
}

// A' build: scale sums by 1/cnt, concat with h, split to bf16 hi|lo
__global__ void convert_A(const float* __restrict__ h, int D) {
    int r4 = 5 * D / 4;
    long i = (long)blockIdx.x * blockDim.x + threadIdx.x;
    if (i >= (long)NN * r4) return;
    int n = (int)(i / r4);
    int col = (int)(i % r4) * 4;
    float4 v;
    if (col < 4 * D) {
        v = *(const float4*)&g_m[(size_t)n * 4 * D + col];
        int t = col / D;
        float inv = 1.0f / fmaxf(g_cnt[(size_t)t * NN + n], 1.0f);
        v.x *= inv; v.y *= inv; v.z *= inv; v.w *= inv;
    } else {
        v = *(const float4*)&h[(size_t)n * D + col - 4 * D];
    }
    int KA = 10 * D;
    __nv_bfloat16 hx = __float2bfloat16_rn(v.x);
    __nv_bfloat16 hy = __float2bfloat16_rn(v.y);
    __nv_bfloat16 hz = __float2bfloat16_rn(v.z);
    __nv_bfloat16 hw = __float2bfloat16_rn(v.w);
    __nv_bfloat162* ph = (__nv_bfloat162*)&g_Abf[(size_t)n * KA + col];
    ph[0] = __halves2bfloat162(hx, hy);
    ph[1] = __halves2bfloat162(hz, hw);
    __nv_bfloat162* pl = (__nv_bfloat162*)&g_Abf[(size_t)n * KA + 5 * D + col];
    pl[0] = __halves2bfloat162(__float2bfloat16_rn(v.x - __bfloat162float(hx)),
                               __float2bfloat16_rn(v.y - __bfloat162float(hy)));
    pl[1] = __halves2bfloat162(__float2bfloat16_rn(v.z - __bfloat162float(hz)),
                               __float2bfloat16_rn(v.w - __bfloat162float(hw)));
}

// ---------------- fp32 SGEMM (tail) ----------------
template <int BN, bool RELU, bool BIAS>
__global__ void __launch_bounds__((128 / 8) * (BN / 8))
sgemm_k(const float* __restrict__ A, int lda, const float* __restrict__ B,
        const float* __restrict__ bias, float* __restrict__ C, int M, int Nn, int K) {
    const int BM = 128, BK = 16, TM = 8, TN = 8;
    const int THREADS = (BM / TM) * (BN / TN);
    __shared__ float As[BK][BM];
    __shared__ float Bs[BK][BN];
    int tid = threadIdx.x;
    int rowC = blockIdx.y * BM, colC = blockIdx.x * BN;
    int tx = tid % (BN / TN);
    int ty = tid / (BN / TN);

    const int A_LOADS = (BM * BK / 4) / THREADS;
    const int B_LOADS = (BK * BN / 4) / THREADS;
    int aRow = tid / (BK / 4);
    int aCol4 = tid % (BK / 4);
    int bRow = tid / (BN / 4);
    int bCol4 = tid % (BN / 4);
    const int A_ROW_STRIDE = THREADS / (BK / 4);
    const int B_ROW_STRIDE = THREADS / (BN / 4);

    float acc[TM][TN] = {};

    for (int k0 = 0; k0 < K; k0 += BK) {
#pragma unroll
        for (int i = 0; i < A_LOADS; i++) {
            int r = aRow + i * A_ROW_STRIDE;
            int grow = rowC + r;
            float4 v = make_float4(0.f, 0.f, 0.f, 0.f);
            if (grow < M) v = *(const float4*)&A[(size_t)grow * lda + k0 + aCol4 * 4];
            As[aCol4 * 4 + 0][r] = v.x;
            As[aCol4 * 4 + 1][r] = v.y;
            As[aCol4 * 4 + 2][r] = v.z;
            As[aCol4 * 4 + 3][r] = v.w;
        }
#pragma unroll
        for (int i = 0; i < B_LOADS; i++) {
            int r = bRow + i * B_ROW_STRIDE;
            *(float4*)&Bs[r][bCol4 * 4] =
                *(const float4*)&B[(size_t)(k0 + r) * Nn + colC + bCol4 * 4];
        }
        __syncthreads();
#pragma unroll
        for (int k = 0; k < BK; k++) {
            float4 a0 = *(const float4*)&As[k][ty * TM];
            float4 a1 = *(const float4*)&As[k][ty * TM + 4];
            float4 b0 = *(const float4*)&Bs[k][tx * TN];
            float4 b1 = *(const float4*)&Bs[k][tx * TN + 4];
            float ar[TM] = {a0.x, a0.y, a0.z, a0.w, a1.x, a1.y, a1.z, a1.w};
            float br[TN] = {b0.x, b0.y, b0.z, b0.w, b1.x, b1.y, b1.z, b1.w};
#pragma unroll
            for (int i = 0; i < TM; i++)
#pragma unroll
                for (int j = 0; j < TN; j++) acc[i][j] += ar[i] * br[j];
        }
        __syncthreads();
    }

#pragma unroll
    for (int i = 0; i < TM; i++) {
        int grow = rowC + ty * TM + i;
        if (grow >= M) continue;
#pragma unroll
        for (int j = 0; j < TN; j += 4) {
            int gcol = colC + tx * TN + j;
            float4 v = make_float4(acc[i][j], acc[i][j + 1], acc[i][j + 2], acc[i][j + 3]);
            if (BIAS) {
                v.x += bias[gcol]; v.y += bias[gcol + 1];
                v.z += bias[gcol + 2]; v.w += bias[gcol + 3];
            }
            if (RELU) {
                v.x = fmaxf(v.x, 0.f); v.y = fmaxf(v.y, 0.f);
                v.z = fmaxf(v.z, 0.f); v.w = fmaxf(v.w, 0.f);
            }
            *(float4*)&C[(size_t)grow * Nn + gcol] = v;
        }
    }
}

// ---------------- tail kernels ----------------
__global__ void pool_combine(float* __restrict__ h, const float* __restrict__ s,
                             const float* __restrict__ cnt) {
    long idx = (long)blockIdx.x * blockDim.x + threadIdx.x;
    if (idx >= (long)NN * 32) return;
    int row = (int)(idx >> 5);
    float inv = 1.0f / fmaxf(cnt[row], 1.0f);
    float4 a = *(float4*)&h[idx * 4];
    float4 b = *(const float4*)&s[idx * 4];
    a.x = (a.x + b.x) * inv; a.y = (a.y + b.y) * inv;
    a.z = (a.z + b.z) * inv; a.w = (a.w + b.w) * inv;
    *(float4*)&h[idx * 4] = a;
}

__global__ void layernorm_k(const float* __restrict__ in, float* __restrict__ out,
                            const float* __restrict__ g, const float* __restrict__ b) {
    int row = blockIdx.x * 8 + (threadIdx.x >> 5);
    int lane = threadIdx.x & 31;
    if (row >= NN) return;
    float4 v = *(const float4*)&in[(size_t)row * 128 + lane * 4];
    float s = v.x + v.y + v.z + v.w;
    float q = v.x * v.x + v.y * v.y + v.z * v.z + v.w * v.w;
#pragma unroll
    for (int o = 16; o; o >>= 1) {
        s += __shfl_xor_sync(0xffffffffu, s, o);
        q += __shfl_xor_sync(0xffffffffu, q, o);
    }
    float mu = s * (1.0f / 128.0f);
    float var = q * (1.0f / 128.0f) - mu * mu;
    float r = rsqrtf(var + 1e-5f);
    float4 gg = *(const float4*)&g[lane * 4];
    float4 bb = *(const float4*)&b[lane * 4];
    float4 o4;
    o4.x = (v.x - mu) * r * gg.x + bb.x;
    o4.y = (v.y - mu) * r * gg.y + bb.y;
    o4.z = (v.z - mu) * r * gg.z + bb.z;
    o4.w = (v.w - mu) * r * gg.w + bb.w;
    *(float4*)&out[(size_t)row * 128 + lane * 4] = o4;
}

__global__ void bn_stats(const float* __restrict__ z) {
    __shared__ float ssum[256], ssq[256];
    int c = threadIdx.x & 63;
    int sub = threadIdx.x >> 6;
    float s = 0.f, q = 0.f;
    for (long r = (long)blockIdx.x * 4 + sub; r < NN; r += (long)gridDim.x * 4) {
        float v = z[r * 64 + c];
        s += v; q += v * v;
    }
    ssum[threadIdx.x] = s; ssq[threadIdx.x] = q;
    __syncthreads();
    if (sub == 0) {
        s = ssum[c] + ssum[64 + c] + ssum[128 + c] + ssum[192 + c];
        q = ssq[c] + ssq[64 + c] + ssq[128 + c] + ssq[192 + c];
        atomicAdd(&g_stats[c], s);
        atomicAdd(&g_stats[64 + c], q);
    }
}

__global__ void finalize_k(const float* __restrict__ z, const float* __restrict__ bn_g,
                           const float* __restrict__ bn_b, const float* __restrict__ cW2,
                           const float* __restrict__ cb2, float* __restrict__ out) {
    __shared__ float w[448], smu[64], sr[64], sg[64], sb[64], sb2[7];
    int tid = threadIdx.x;
    for (int i = tid; i < 448; i += blockDim.x) w[i] = cW2[i];
    if (tid < 64) {
        float mu = g_stats[tid] / (float)NN;
        float var = g_stats[64 + tid] / (float)NN - mu * mu;
        smu[tid] = mu;
        sr[tid] = rsqrtf(var + 1e-5f);
        sg[tid] = bn_g[tid];
        sb[tid] = bn_b[tid];
    }
    if (tid < 7) sb2[tid] = cb2[tid];
    __syncthreads();
    int row = blockIdx.x * blockDim.x + tid;
    if (row >= NN) return;
    float logits[7];
#pragma unroll
    for (int j = 0; j < 7; j++) logits[j] = sb2[j];
    for (int c = 0; c < 64; c += 4) {
        float4 v4 = *(const float4*)&z[(size_t)row * 64 + c];
        float vv[4] = {v4.x, v4.y, v4.z, v4.w};
#pragma unroll
        for (int u = 0; u < 4; u++) {
            int cc = c + u;
            float v = (vv[u] - smu[cc]) * sr[cc] * sg[cc] + sb[cc];
#pragma unroll
            for (int j = 0; j < 7; j++) logits[j] += v * w[cc * 7 + j];
        }
    }
    float m = logits[0];
#pragma unroll
    for (int j = 1; j < 7; j++) m = fmaxf(m, logits[j]);
    float ssum = 0.f;
#pragma unroll
    for (int j = 0; j < 7; j++) { logits[j] = expf(logits[j] - m); ssum += logits[j]; }
    float inv = 1.0f / ssum;
#pragma unroll
    for (int j = 0; j < 7; j++) out[(size_t)row * 7 + j] = logits[j] * inv;
}

// ---------------- host launcher ----------------
static inline int cdiv(long a, int b) { return (int)((a + b - 1) / b); }

extern "C" void kernel_launch(void* const* d_in, const int* in_sizes, int n_in,
                              void* d_out, int out_size) {
    const float* x = (const float*)d_in[0];
    const int* edges[4] = {(const int*)d_in[1], (const int*)d_in[2],
                           (const int*)d_in[3], (const int*)d_in[4]};
    const float* Wl0 = (const float*)d_in[5];
    const float* bl0 = (const float*)d_in[6];
    const float* Wr0 = (const float*)d_in[7];
    const float* Wl = (const float*)d_in[8];
    const float* bl = (const float*)d_in[9];
    const float* Wr = (const float*)d_in[10];
    const float* lin_W = (const float*)d_in[11];
    const float* lin_b = (const float*)d_in[12];
    const float* norm_g = (const float*)d_in[13];
    const float* norm_b = (const float*)d_in[14];
    const float* pW1 = (const float*)d_in[15];
    const float* pb1 = (const float*)d_in[16];
    const float* pln_g = (const float*)d_in[17];
    const float* pln_b = (const float*)d_in[18];
    const float* pW2 = (const float*)d_in[19];
    const float* pb2 = (const float*)d_in[20];
    const float* cW1 = (const float*)d_in[21];
    const float* cb1 = (const float*)d_in[22];
    const float* bn_g = (const float*)d_in[23];
    const float* bn_b = (const float*)d_in[24];
    const float* cW2 = (const float*)d_in[25];
    const float* cb2 = (const float*)d_in[26];
    float* out = (float*)d_out;

    float *pm, *pbias, *ph, *ph2, *pcnt, *pstats;
    __nv_bfloat16 *pAbf, *pBbf;
    cudaGetSymbolAddress((void**)&pm, g_m);
    cudaGetSymbolAddress((void**)&pAbf, g_Abf);
    cudaGetSymbolAddress((void**)&pBbf, g_Bbf);
    cudaGetSymbolAddress((void**)&pbias, g_bias);
    cudaGetSymbolAddress((void**)&ph, g_h);
    cudaGetSymbolAddress((void**)&ph2, g_h2);
    cudaGetSymbolAddress((void**)&pcnt, g_cnt);
    cudaGetSymbolAddress((void**)&pstats, g_stats);

    const int T = 256;
    const dim3 GEMM_GRID(cdiv(NN, 128), 2);

    // in-degree counts per relation
    zero_buf<<<cdiv(4L * NN, T), T>>>(pcnt, 4L * NN);
    for (int t = 0; t < 4; t++)
        count_k<<<cdiv(EE, T), T>>>(edges[t], pcnt + (size_t)t * NN);

    // ---- Layer 0 (Din = 128) ----
    build_Bbf<<<cdiv(5L * 128 * 256, T), T>>>(Wl0, Wr0, bl0, 128);
    zero_buf<<<cdiv((long)NN * 512, T), T>>>(pm, (long)NN * 512);
    for (int t = 0; t < 4; t++)
        scatter_k<32><<<cdiv((long)EE * 32, T), T>>>(edges[t], x, pm, 512, t * 128);
    convert_A<<<cdiv((long)NN * 160, T), T>>>(x, 128);
    mma_gemm<<<GEMM_GRID, 256>>>(pAbf, 1280, pBbf, 1920, pbias, ph, 20, 60);

    // ---- Layers 1, 2 (Din = 256) ----
    float* hin = ph;
    float* hout = ph2;
    for (int l = 0; l < 2; l++) {
        build_Bbf<<<cdiv(5L * 256 * 256, T), T>>>(Wl + (size_t)l * 4 * 256 * 256,
                                                  Wr + (size_t)l * 4 * 256 * 256,
                                                  bl + (size_t)l * 4 * 256, 256);
        zero_buf<<<cdiv((long)NN * 1024, T), T>>>(pm, (long)NN * 1024);
        for (int t = 0; t < 4; t++)
            scatter_k<64><<<cdiv((long)EE * 64, T), T>>>(edges[t], hin, pm, 1024, t * 256);
        convert_A<<<cdiv((long)NN * 320, T), T>>>(hin, 256);
        mma_gemm<<<GEMM_GRID, 256>>>(pAbf, 2560, pBbf, 3840, pbias, hout, 40, 120);
        float* tmp = hin; hin = hout; hout = tmp;
    }
    // GNN output now in hin == ph

    // lin: [N,256] @ [256,128] + b
    sgemm_k<128, false, true><<<dim3(1, cdiv(NN, 128)), 256>>>(hin, 256, lin_W, lin_b, ph2, NN, 128, 256);

    // onset pooling: s = scatter_sum(h[src], dst); h = (h + s)/max(c0,1)
    zero_buf<<<cdiv((long)NN * 128, T), T>>>(pm, (long)NN * 128);
    scatter_k<32><<<cdiv((long)EE * 32, T), T>>>(edges[0], ph2, pm, 128, 0);
    pool_combine<<<cdiv((long)NN * 32, T), T>>>(ph2, pm, pcnt);

    // layernorm
    layernorm_k<<<cdiv(NN, 8), 256>>>(ph2, ph, norm_g, norm_b);
    // pool_mlp
    sgemm_k<128, true, true><<<dim3(1, cdiv(NN, 128)), 256>>>(ph, 128, pW1, pb1, ph2, NN, 128, 128);
    layernorm_k<<<cdiv(NN, 8), 256>>>(ph2, ph, pln_g, pln_b);
    sgemm_k<128, false, true><<<dim3(1, cdiv(NN, 128)), 256>>>(ph, 128, pW2, pb2, ph2, NN, 128, 128);
    // clf first layer + relu
    sgemm_k<64, true, true><<<dim3(1, cdiv(NN, 128)), 128>>>(ph2, 128, cW1, cb1, ph, NN, 64, 128);
    // batchnorm stats + fused finalize
    zero_buf<<<1, 128>>>(pstats, 128);
    bn_stats<<<512, 256>>>(ph);
    finalize_k<<<cdiv(NN, 256), 256>>>(ph, bn_g, bn_b, cW2, cb2, out);
}

// round 4
// speedup vs baseline: 2.1574x; 1.6994x over previous
#include <cuda_runtime.h>
#include <cuda_bf16.h>
#include <cstdint>

#define NN 50000
#define EE 500000

// ---------------- scratch (static device globals; no runtime allocation) ----------------
__device__ __align__(16) float g_m[(size_t)NN * 128];               // pooling temp
__device__ __align__(16) __nv_bfloat16 g_Abf[(size_t)NN * 2560];    // A' = [hi(5D) | lo(5D)], KA = 10D
__device__ __align__(16) __nv_bfloat16 g_Bbf[(size_t)256 * 3840];   // B' = [Bhi; Blo; Bhi], K3 = 15D
__device__ __align__(16) float g_bias[256];
__device__ __align__(16) float g_h[(size_t)NN * 256];
__device__ __align__(16) float g_h2[(size_t)NN * 256];
__device__ __align__(16) float g_stats[128];
// CSR
__device__ int g_off[4 * (NN + 1)];
__device__ int g_list[4 * EE];
__device__ int g_cur[4 * NN];

// ---------------- helpers ----------------
__device__ __forceinline__ uint32_t smem_u32(const void* p) {
    uint32_t a;
    asm("{ .reg .u64 t; cvta.to.shared.u64 t, %1; cvt.u32.u64 %0, t; }" : "=r"(a) : "l"(p));
    return a;
}
__device__ __forceinline__ void cp_async16(uint32_t dst, const void* src, int sz) {
    asm volatile("cp.async.cg.shared.global [%0], [%1], 16, %2;"
                 :: "r"(dst), "l"(src), "r"(sz) : "memory");
}
__device__ __forceinline__ void cp_commit() { asm volatile("cp.async.commit_group;" ::: "memory"); }
template <int Nw>
__device__ __forceinline__ void cp_wait() { asm volatile("cp.async.wait_group %0;" ::"n"(Nw) : "memory"); }

__device__ __forceinline__ uint32_t pack_bf2(__nv_bfloat16 a, __nv_bfloat16 b) {
    __nv_bfloat162 t = __halves2bfloat162(a, b);
    return *(uint32_t*)&t;
}

// ---------------- CSR build ----------------
__global__ void zero_int(int* __restrict__ p, int n) {
    int i = blockIdx.x * blockDim.x + threadIdx.x;
    if (i < n) p[i] = 0;
}

__global__ void hist_k(const int* __restrict__ e0, const int* __restrict__ e1,
                       const int* __restrict__ e2, const int* __restrict__ e3) {
    int t = blockIdx.y;
    const int* e = (t == 0) ? e0 : (t == 1) ? e1 : (t == 2) ? e2 : e3;
    int i = blockIdx.x * blockDim.x + threadIdx.x;
    if (i < EE) atomicAdd(&g_cur[t * NN + e[EE + i]], 1);
}

// one block per relation; exclusive scan of 50000 counts -> offsets
__global__ void __launch_bounds__(1024) scan_k() {
    int t = blockIdx.x;
    const int C = (NN + 1023) / 1024;  // 49
    __shared__ int part[1024];
    int start = threadIdx.x * C;
    int s = 0;
    for (int i = 0; i < C; i++) {
        int j = start + i;
        if (j < NN) s += g_cur[t * NN + j];
    }
    part[threadIdx.x] = s;
    __syncthreads();
    if (threadIdx.x == 0) {
        int a = 0;
        for (int i = 0; i < 1024; i++) { int v = part[i]; part[i] = a; a += v; }
    }
    __syncthreads();
    int a = part[threadIdx.x];
    for (int i = 0; i < C; i++) {
        int j = start + i;
        if (j < NN) {
            g_off[t * (NN + 1) + j] = a;
            a += g_cur[t * NN + j];
        }
    }
    if (threadIdx.x == 0) g_off[t * (NN + 1) + NN] = EE;
}

__global__ void copy_cursor() {
    int i = blockIdx.x * blockDim.x + threadIdx.x;
    if (i < 4 * NN) {
        int t = i / NN, j = i - t * NN;
        g_cur[i] = g_off[t * (NN + 1) + j];
    }
}

__global__ void fill_k(const int* __restrict__ e0, const int* __restrict__ e1,
                       const int* __restrict__ e2, const int* __restrict__ e3) {
    int t = blockIdx.y;
    const int* e = (t == 0) ? e0 : (t == 1) ? e1 : (t == 2) ? e2 : e3;
    int i = blockIdx.x * blockDim.x + threadIdx.x;
    if (i < EE) {
        int d = e[EE + i];
        int p = atomicAdd(&g_cur[t * NN + d], 1);
        g_list[t * EE + p] = e[i];
    }
}

// ---------------- CSR gather-aggregate: mean over neighbors -> bf16 hi/lo into g_Abf ----------------
// one warp per (relation, node); VP floats per lane (D = 32*VP)
template <int VP>
__global__ void __launch_bounds__(256) aggregate_k(const float* __restrict__ h) {
    const int D = 32 * VP, KA = 10 * D;
    int wid = threadIdx.x >> 5, lane = threadIdx.x & 31;
    int n = blockIdx.x * 8 + wid;
    int t = blockIdx.y;
    if (n >= NN) return;
    int beg = g_off[t * (NN + 1) + n], end = g_off[t * (NN + 1) + n + 1];
    float acc[VP];
#pragma unroll
    for (int i = 0; i < VP; i++) acc[i] = 0.f;
    const int* lst = g_list + (size_t)t * EE;
    for (int e = beg; e < end; e++) {
        int s = __ldg(&lst[e]);
        const float4* src = (const float4*)(h + (size_t)s * D + lane * VP);
#pragma unroll
        for (int q = 0; q < VP / 4; q++) {
            float4 v = __ldg(&src[q]);
            acc[q * 4 + 0] += v.x; acc[q * 4 + 1] += v.y;
            acc[q * 4 + 2] += v.z; acc[q * 4 + 3] += v.w;
        }
    }
    float inv = 1.0f / fmaxf((float)(end - beg), 1.0f);
    uint32_t hw[VP / 2], lw[VP / 2];
#pragma unroll
    for (int i = 0; i < VP / 2; i++) {
        float v0 = acc[2 * i] * inv, v1 = acc[2 * i + 1] * inv;
        __nv_bfloat16 h0 = __float2bfloat16_rn(v0);
        __nv_bfloat16 h1 = __float2bfloat16_rn(v1);
        hw[i] = pack_bf2(h0, h1);
        lw[i] = pack_bf2(__float2bfloat16_rn(v0 - __bfloat162float(h0)),
                         __float2bfloat16_rn(v1 - __bfloat162float(h1)));
    }
    __nv_bfloat16* dhi = g_Abf + (size_t)n * KA + t * D + lane * VP;
    __nv_bfloat16* dlo = dhi + 5 * D;
    if (VP == 8) {
        *(uint4*)dhi = make_uint4(hw[0], hw[1], hw[2], hw[3]);
        *(uint4*)dlo = make_uint4(lw[0], lw[1], lw[2], lw[3]);
    } else {
        *(uint2*)dhi = make_uint2(hw[0], hw[1]);
        *(uint2*)dlo = make_uint2(lw[0], lw[1]);
    }
}

// self part: h -> bf16 hi/lo at columns [4D,5D) and [9D,10D)
__global__ void convert_self(const float* __restrict__ h, int D) {
    int r4 = D / 4;
    long i = (long)blockIdx.x * blockDim.x + threadIdx.x;
    if (i >= (long)NN * r4) return;
    int n = (int)(i / r4);
    int c = (int)(i % r4) * 4;
    float4 v = *(const float4*)&h[(size_t)n * D + c];
    int KA = 10 * D;
    __nv_bfloat16 hx = __float2bfloat16_rn(v.x);
    __nv_bfloat16 hy = __float2bfloat16_rn(v.y);
    __nv_bfloat16 hz = __float2bfloat16_rn(v.z);
    __nv_bfloat16 hw4 = __float2bfloat16_rn(v.w);
    uint2 hv = make_uint2(pack_bf2(hx, hy), pack_bf2(hz, hw4));
    uint2 lv = make_uint2(
        pack_bf2(__float2bfloat16_rn(v.x - __bfloat162float(hx)),
                 __float2bfloat16_rn(v.y - __bfloat162float(hy))),
        pack_bf2(__float2bfloat16_rn(v.z - __bfloat162float(hz)),
                 __float2bfloat16_rn(v.w - __bfloat162float(hw4))));
    *(uint2*)(g_Abf + (size_t)n * KA + 4 * D + c) = hv;
    *(uint2*)(g_Abf + (size_t)n * KA + 9 * D + c) = lv;
}

// ---------------- bf16 mma.sync GEMM ----------------
#define BKC 32
__global__ void __launch_bounds__(256, 2)
mma_gemm(const __nv_bfloat16* __restrict__ A, int KA,
         const __nv_bfloat16* __restrict__ B, int K3,
         const float* __restrict__ bias, float* __restrict__ C,
         int NCb, int NC) {
    __shared__ __nv_bfloat16 As[2][128][40];
    __shared__ __nv_bfloat16 Bs[2][128][40];
    int tid = threadIdx.x;
    int wid = tid >> 5, lane = tid & 31;
    int t4 = lane >> 2, tq = lane & 3;
    int warp_m = wid & 3;
    int warp_n = wid >> 2;
    int rowBase = blockIdx.x * 128;
    int colC = blockIdx.y * 128;
    int m0 = warp_m * 32, n0 = warp_n * 64;

    float acc[2][8][4];
#pragma unroll
    for (int i = 0; i < 2; i++)
#pragma unroll
        for (int j = 0; j < 8; j++)
#pragma unroll
            for (int q = 0; q < 4; q++) acc[i][j][q] = 0.f;

    auto issue = [&](int c, int s) {
        int ac = (c < NCb) ? c : c - NCb;
#pragma unroll
        for (int i = 0; i < 2; i++) {
            int u = tid + i * 256;
            int r = u >> 2, q = u & 3;
            int gr = rowBase + r;
            const __nv_bfloat16* srcA = A + (size_t)gr * KA + ac * BKC + q * 8;
            cp_async16(smem_u32(&As[s][r][q * 8]), srcA, gr < NN ? 16 : 0);
            const __nv_bfloat16* srcB = B + (size_t)(colC + r) * K3 + c * BKC + q * 8;
            cp_async16(smem_u32(&Bs[s][r][q * 8]), srcB, 16);
        }
        cp_commit();
    };

    issue(0, 0);

    for (int c = 0; c < NC; c++) {
        int s = c & 1;
        if (c + 1 < NC) {
            issue(c + 1, s ^ 1);
            cp_wait<1>();
        } else {
            cp_wait<0>();
        }
        __syncthreads();

        const __nv_bfloat16(*as)[40] = As[s];
        const __nv_bfloat16(*bs)[40] = Bs[s];
#pragma unroll
        for (int ks = 0; ks < 2; ks++) {
            uint32_t a[2][4], b[8][2];
#pragma unroll
            for (int im = 0; im < 2; im++) {
                int rm = m0 + im * 16 + t4;
                int kc = ks * 16 + tq * 2;
                a[im][0] = *(const uint32_t*)&as[rm][kc];
                a[im][1] = *(const uint32_t*)&as[rm + 8][kc];
                a[im][2] = *(const uint32_t*)&as[rm][kc + 8];
                a[im][3] = *(const uint32_t*)&as[rm + 8][kc + 8];
            }
#pragma unroll
            for (int in = 0; in < 8; in++) {
                int rn = n0 + in * 8 + t4;
                int kc = ks * 16 + tq * 2;
                b[in][0] = *(const uint32_t*)&bs[rn][kc];
                b[in][1] = *(const uint32_t*)&bs[rn][kc + 8];
            }
#pragma unroll
            for (int im = 0; im < 2; im++)
#pragma unroll
                for (int in = 0; in < 8; in++) {
                    asm volatile(
                        "mma.sync.aligned.m16n8k16.row.col.f32.bf16.bf16.f32 "
                        "{%0,%1,%2,%3}, {%4,%5,%6,%7}, {%8,%9}, {%0,%1,%2,%3};"
                        : "+f"(acc[im][in][0]), "+f"(acc[im][in][1]),
                          "+f"(acc[im][in][2]), "+f"(acc[im][in][3])
                        : "r"(a[im][0]), "r"(a[im][1]), "r"(a[im][2]), "r"(a[im][3]),
                          "r"(b[in][0]), "r"(b[in][1]));
                }
        }
        __syncthreads();
    }

#pragma unroll
    for (int im = 0; im < 2; im++) {
        int gr0 = rowBase + m0 + im * 16 + t4;
#pragma unroll
        for (int in = 0; in < 8; in++) {
            int col = colC + n0 + in * 8 + tq * 2;
            float bx = bias[col], by = bias[col + 1];
            if (gr0 < NN) {
                float2 v = make_float2(fmaxf(acc[im][in][0] + bx, 0.f),
                                       fmaxf(acc[im][in][1] + by, 0.f));
                *(float2*)&C[(size_t)gr0 * 256 + col] = v;
            }
            if (gr0 + 8 < NN) {
                float2 v = make_float2(fmaxf(acc[im][in][2] + bx, 0.f),
                                       fmaxf(acc[im][in][3] + by, 0.f));
                *(float2*)&C[(size_t)(gr0 + 8) * 256 + col] = v;
            }
        }
    }
}

// ---------------- misc ----------------
__global__ void zero_buf(float* __restrict__ p, long n) {
    long i = (long)blockIdx.x * blockDim.x + threadIdx.x;
    if (i < n) p[i] = 0.0f;
}

// Build B' (bf16 hi/lo stacked) + summed bias
__global__ void build_Bbf(const float* __restrict__ Wl, const float* __restrict__ Wr,
                          const float* __restrict__ bl, int D) {
    long i = (long)blockIdx.x * blockDim.x + threadIdx.x;
    long total = (long)5 * D * 256;
    if (i >= total) return;
    int k = (int)(i / 256), n = (int)(i % 256);
    float v;
    if (k < 4 * D) {
        v = Wl[(size_t)k * 256 + n];
    } else {
        int kk = k - 4 * D;
        v = Wr[(size_t)kk * 256 + n] + Wr[((size_t)D + kk) * 256 + n] +
            Wr[((size_t)2 * D + kk) * 256 + n] + Wr[((size_t)3 * D + kk) * 256 + n];
    }
    int K3 = 15 * D;
    __nv_bfloat16 hi = __float2bfloat16_rn(v);
    __nv_bfloat16 lo = __float2bfloat16_rn(v - __bfloat162float(hi));
    g_Bbf[(size_t)n * K3 + k] = hi;
    g_Bbf[(size_t)n * K3 + 5 * D + k] = lo;
    g_Bbf[(size_t)n * K3 + 10 * D + k] = hi;
    if (i < 256) g_bias[i] = bl[i] + bl[256 + i] + bl[512 + i] + bl[768 + i];
}

// ---------------- fp32 SGEMM (tail) ----------------
template <int BN, bool RELU, bool BIAS>
__global__ void __launch_bounds__((128 / 8) * (BN / 8))
sgemm_k(const float* __restrict__ A, int lda, const float* __restrict__ B,
        const float* __restrict__ bias, float* __restrict__ C, int M, int Nn, int K) {
    const int BM = 128, BK = 16, TM = 8, TN = 8;
    const int THREADS = (BM / TM) * (BN / TN);
    __shared__ float As[BK][BM];
    __shared__ float Bs[BK][BN];
    int tid = threadIdx.x;
    int rowC = blockIdx.y * BM, colC = blockIdx.x * BN;
    int tx = tid % (BN / TN);
    int ty = tid / (BN / TN);

    const int A_LOADS = (BM * BK / 4) / THREADS;
    const int B_LOADS = (BK * BN / 4) / THREADS;
    int aRow = tid / (BK / 4);
    int aCol4 = tid % (BK / 4);
    int bRow = tid / (BN / 4);
    int bCol4 = tid % (BN / 4);
    const int A_ROW_STRIDE = THREADS / (BK / 4);
    const int B_ROW_STRIDE = THREADS / (BN / 4);

    float acc[TM][TN] = {};

    for (int k0 = 0; k0 < K; k0 += BK) {
#pragma unroll
        for (int i = 0; i < A_LOADS; i++) {
            int r = aRow + i * A_ROW_STRIDE;
            int grow = rowC + r;
            float4 v = make_float4(0.f, 0.f, 0.f, 0.f);
            if (grow < M) v = *(const float4*)&A[(size_t)grow * lda + k0 + aCol4 * 4];
            As[aCol4 * 4 + 0][r] = v.x;
            As[aCol4 * 4 + 1][r] = v.y;
            As[aCol4 * 4 + 2][r] = v.z;
            As[aCol4 * 4 + 3][r] = v.w;
        }
#pragma unroll
        for (int i = 0; i < B_LOADS; i++) {
            int r = bRow + i * B_ROW_STRIDE;
            *(float4*)&Bs[r][bCol4 * 4] =
                *(const float4*)&B[(size_t)(k0 + r) * Nn + colC + bCol4 * 4];
        }
        __syncthreads();
#pragma unroll
        for (int k = 0; k < BK; k++) {
            float4 a0 = *(const float4*)&As[k][ty * TM];
            float4 a1 = *(const float4*)&As[k][ty * TM + 4];
            float4 b0 = *(const float4*)&Bs[k][tx * TN];
            float4 b1 = *(const float4*)&Bs[k][tx * TN + 4];
            float ar[TM] = {a0.x, a0.y, a0.z, a0.w, a1.x, a1.y, a1.z, a1.w};
            float br[TN] = {b0.x, b0.y, b0.z, b0.w, b1.x, b1.y, b1.z, b1.w};
#pragma unroll
            for (int i = 0; i < TM; i++)
#pragma unroll
                for (int j = 0; j < TN; j++) acc[i][j] += ar[i] * br[j];
        }
        __syncthreads();
    }

#pragma unroll
    for (int i = 0; i < TM; i++) {
        int grow = rowC + ty * TM + i;
        if (grow >= M) continue;
#pragma unroll
        for (int j = 0; j < TN; j += 4) {
            int gcol = colC + tx * TN + j;
            float4 v = make_float4(acc[i][j], acc[i][j + 1], acc[i][j + 2], acc[i][j + 3]);
            if (BIAS) {
                v.x += bias[gcol]; v.y += bias[gcol + 1];
                v.z += bias[gcol + 2]; v.w += bias[gcol + 3];
            }
            if (RELU) {
                v.x = fmaxf(v.x, 0.f); v.y = fmaxf(v.y, 0.f);
                v.z = fmaxf(v.z, 0.f); v.w = fmaxf(v.w, 0.f);
            }
            *(float4*)&C[(size_t)grow * Nn + gcol] = v;
        }
    }
}

// ---------------- tail kernels ----------------
// onset pool via relation-0 CSR gather: out[n] = (h[n] + sum_{src->n} h[src]) / max(deg,1)
__global__ void __launch_bounds__(256) pool_gather(const float* __restrict__ hin,
                                                   float* __restrict__ hout) {
    int wid = threadIdx.x >> 5, lane = threadIdx.x & 31;
    int n = blockIdx.x * 8 + wid;
    if (n >= NN) return;
    int beg = g_off[n], end = g_off[n + 1];
    float4 acc = *(const float4*)&hin[(size_t)n * 128 + lane * 4];
    for (int e = beg; e < end; e++) {
        int s = __ldg(&g_list[e]);
        float4 v = __ldg((const float4*)&hin[(size_t)s * 128 + lane * 4]);
        acc.x += v.x; acc.y += v.y; acc.z += v.z; acc.w += v.w;
    }
    float inv = 1.0f / fmaxf((float)(end - beg), 1.0f);
    acc.x *= inv; acc.y *= inv; acc.z *= inv; acc.w *= inv;
    *(float4*)&hout[(size_t)n * 128 + lane * 4] = acc;
}

__global__ void layernorm_k(const float* __restrict__ in, float* __restrict__ out,
                            const float* __restrict__ g, const float* __restrict__ b) {
    int row = blockIdx.x * 8 + (threadIdx.x >> 5);
    int lane = threadIdx.x & 31;
    if (row >= NN) return;
    float4 v = *(const float4*)&in[(size_t)row * 128 + lane * 4];
    float s = v.x + v.y + v.z + v.w;
    float q = v.x * v.x + v.y * v.y + v.z * v.z + v.w * v.w;
#pragma unroll
    for (int o = 16; o; o >>= 1) {
        s += __shfl_xor_sync(0xffffffffu, s, o);
        q += __shfl_xor_sync(0xffffffffu, q, o);
    }
    float mu = s * (1.0f / 128.0f);
    float var = q * (1.0f / 128.0f) - mu * mu;
    float r = rsqrtf(var + 1e-5f);
    float4 gg = *(const float4*)&g[lane * 4];
    float4 bb = *(const float4*)&b[lane * 4];
    float4 o4;
    o4.x = (v.x - mu) * r * gg.x + bb.x;
    o4.y = (v.y - mu) * r * gg.y + bb.y;
    o4.z = (v.z - mu) * r * gg.z + bb.z;
    o4.w = (v.w - mu) * r * gg.w + bb.w;
    *(float4*)&out[(size_t)row * 128 + lane * 4] = o4;
}

__global__ void bn_stats(const float* __restrict__ z) {
    __shared__ float ssum[256], ssq[256];
    int c = threadIdx.x & 63;
    int sub = threadIdx.x >> 6;
    float s = 0.f, q = 0.f;
    for (long r = (long)blockIdx.x * 4 + sub; r < NN; r += (long)gridDim.x * 4) {
        float v = z[r * 64 + c];
        s += v; q += v * v;
    }
    ssum[threadIdx.x] = s; ssq[threadIdx.x] = q;
    __syncthreads();
    if (sub == 0) {
        s = ssum[c] + ssum[64 + c] + ssum[128 + c] + ssum[192 + c];
        q = ssq[c] + ssq[64 + c] + ssq[128 + c] + ssq[192 + c];
        atomicAdd(&g_stats[c], s);
        atomicAdd(&g_stats[64 + c], q);
    }
}

__global__ void finalize_k(const float* __restrict__ z, const float* __restrict__ bn_g,
                           const float* __restrict__ bn_b, const float* __restrict__ cW2,
                           const float* __restrict__ cb2, float* __restrict__ out) {
    __shared__ float w[448], smu[64], sr[64], sg[64], sb[64], sb2[7];
    int tid = threadIdx.x;
    for (int i = tid; i < 448; i += blockDim.x) w[i] = cW2[i];
    if (tid < 64) {
        float mu = g_stats[tid] / (float)NN;
        float var = g_stats[64 + tid] / (float)NN - mu * mu;
        smu[tid] = mu;
        sr[tid] = rsqrtf(var + 1e-5f);
        sg[tid] = bn_g[tid];
        sb[tid] = bn_b[tid];
    }
    if (tid < 7) sb2[tid] = cb2[tid];
    __syncthreads();
    int row = blockIdx.x * blockDim.x + tid;
    if (row >= NN) return;
    float logits[7];
#pragma unroll
    for (int j = 0; j < 7; j++) logits[j] = sb2[j];
    for (int c = 0; c < 64; c += 4) {
        float4 v4 = *(const float4*)&z[(size_t)row * 64 + c];
        float vv[4] = {v4.x, v4.y, v4.z, v4.w};
#pragma unroll
        for (int u = 0; u < 4; u++) {
            int cc = c + u;
            float v = (vv[u] - smu[cc]) * sr[cc] * sg[cc] + sb[cc];
#pragma unroll
            for (int j = 0; j < 7; j++) logits[j] += v * w[cc * 7 + j];
        }
    }
    float m = logits[0];
#pragma unroll
    for (int j = 1; j < 7; j++) m = fmaxf(m, logits[j]);
    float ssum = 0.f;
#pragma unroll
    for (int j = 0; j < 7; j++) { logits[j] = expf(logits[j] - m); ssum += logits[j]; }
    float inv = 1.0f / ssum;
#pragma unroll
    for (int j = 0; j < 7; j++) out[(size_t)row * 7 + j] = logits[j] * inv;
}

// ---------------- host launcher ----------------
static inline int cdiv(long a, int b) { return (int)((a + b - 1) / b); }

extern "C" void kernel_launch(void* const* d_in, const int* in_sizes, int n_in,
                              void* d_out, int out_size) {
    const float* x = (const float*)d_in[0];
    const int* e0 = (const int*)d_in[1];
    const int* e1 = (const int*)d_in[2];
    const int* e2 = (const int*)d_in[3];
    const int* e3 = (const int*)d_in[4];
    const float* Wl0 = (const float*)d_in[5];
    const float* bl0 = (const float*)d_in[6];
    const float* Wr0 = (const float*)d_in[7];
    const float* Wl = (const float*)d_in[8];
    const float* bl = (const float*)d_in[9];
    const float* Wr = (const float*)d_in[10];
    const float* lin_W = (const float*)d_in[11];
    const float* lin_b = (const float*)d_in[12];
    const float* norm_g = (const float*)d_in[13];
    const float* norm_b = (const float*)d_in[14];
    const float* pW1 = (const float*)d_in[15];
    const float* pb1 = (const float*)d_in[16];
    const float* pln_g = (const float*)d_in[17];
    const float* pln_b = (const float*)d_in[18];
    const float* pW2 = (const float*)d_in[19];
    const float* pb2 = (const float*)d_in[20];
    const float* cW1 = (const float*)d_in[21];
    const float* cb1 = (const float*)d_in[22];
    const float* bn_g = (const float*)d_in[23];
    const float* bn_b = (const float*)d_in[24];
    const float* cW2 = (const float*)d_in[25];
    const float* cb2 = (const float*)d_in[26];
    float* out = (float*)d_out;

    float *pm, *pbias, *ph, *ph2, *pstats;
    __nv_bfloat16 *pAbf, *pBbf;
    int* pcur;
    cudaGetSymbolAddress((void**)&pm, g_m);
    cudaGetSymbolAddress((void**)&pAbf, g_Abf);
    cudaGetSymbolAddress((void**)&pBbf, g_Bbf);
    cudaGetSymbolAddress((void**)&pbias, g_bias);
    cudaGetSymbolAddress((void**)&ph, g_h);
    cudaGetSymbolAddress((void**)&ph2, g_h2);
    cudaGetSymbolAddress((void**)&pstats, g_stats);
    cudaGetSymbolAddress((void**)&pcur, g_cur);

    const int T = 256;
    const dim3 GEMM_GRID(cdiv(NN, 128), 2);
    const dim3 AGG_GRID(cdiv(NN, 8), 4);
    const dim3 EDGE_GRID(cdiv(EE, T), 4);

    // ---- CSR build (edges constant across layers) ----
    zero_int<<<cdiv(4L * NN, T), T>>>(pcur, 4 * NN);
    hist_k<<<EDGE_GRID, T>>>(e0, e1, e2, e3);
    scan_k<<<4, 1024>>>();
    copy_cursor<<<cdiv(4L * NN, T), T>>>();
    fill_k<<<EDGE_GRID, T>>>(e0, e1, e2, e3);

    // ---- Layer 0 (D = 128) ----
    build_Bbf<<<cdiv(5L * 128 * 256, T), T>>>(Wl0, Wr0, bl0, 128);
    aggregate_k<4><<<AGG_GRID, 256>>>(x);
    convert_self<<<cdiv((long)NN * 32, T), T>>>(x, 128);
    mma_gemm<<<GEMM_GRID, 256>>>(pAbf, 1280, pBbf, 1920, pbias, ph, 20, 60);

    // ---- Layers 1, 2 (D = 256) ----
    float* hin = ph;
    float* hout = ph2;
    for (int l = 0; l < 2; l++) {
        build_Bbf<<<cdiv(5L * 256 * 256, T), T>>>(Wl + (size_t)l * 4 * 256 * 256,
                                                  Wr + (size_t)l * 4 * 256 * 256,
                                                  bl + (size_t)l * 4 * 256, 256);
        aggregate_k<8><<<AGG_GRID, 256>>>(hin);
        convert_self<<<cdiv((long)NN * 64, T), T>>>(hin, 256);
        mma_gemm<<<GEMM_GRID, 256>>>(pAbf, 2560, pBbf, 3840, pbias, hout, 40, 120);
        float* tmp = hin; hin = hout; hout = tmp;
    }
    // GNN output in hin == ph

    // lin: [N,256] @ [256,128] + b
    sgemm_k<128, false, true><<<dim3(1, cdiv(NN, 128)), 256>>>(hin, 256, lin_W, lin_b, ph2, NN, 128, 256);

    // onset pooling via CSR gather (relation 0)
    pool_gather<<<cdiv(NN, 8), 256>>>(ph2, pm);

    // layernorm + pool_mlp + clf
    layernorm_k<<<cdiv(NN, 8), 256>>>(pm, ph, norm_g, norm_b);
    sgemm_k<128, true, true><<<dim3(1, cdiv(NN, 128)), 256>>>(ph, 128, pW1, pb1, ph2, NN, 128, 128);
    layernorm_k<<<cdiv(NN, 8), 256>>>(ph2, ph, pln_g, pln_b);
    sgemm_k<128, false, true><<<dim3(1, cdiv(NN, 128)), 256>>>(ph, 128, pW2, pb2, ph2, NN, 128, 128);
    sgemm_k<64, true, true><<<dim3(1, cdiv(NN, 128)), 128>>>(ph2, 128, cW1, cb1, ph, NN, 64, 128);
    zero_buf<<<1, 128>>>(pstats, 128);
    bn_stats<<<512, 256>>>(ph);
    finalize_k<<<cdiv(NN, 256), 256>>>(ph, bn_g, bn_b, cW2, cb2, out);
}

// round 5
// speedup vs baseline: 2.1963x; 1.0180x over previous
#include <cuda_runtime.h>
#include <cuda_bf16.h>
#include <cstdint>

#define NN 50000
#define EE 500000

// ---------------- scratch (static device globals; no runtime allocation) ----------------
__device__ __align__(16) float g_m[(size_t)NN * 128];               // pooling temp
__device__ __align__(16) __nv_bfloat16 g_Abf[(size_t)NN * 2560];    // A' = [hi | lo]
__device__ __align__(16) __nv_bfloat16 g_Bbf[(size_t)256 * 3840];   // main B' = [Bhi; Blo; Bhi]
__device__ __align__(16) __nv_bfloat16 g_Bt[(size_t)128 * 768];     // tail B'
__device__ __align__(16) float g_bias[256];
__device__ __align__(16) float g_h[(size_t)NN * 256];
__device__ __align__(16) float g_h2[(size_t)NN * 256];
__device__ __align__(16) float g_stats[128];
// CSR
__device__ int g_off[4 * (NN + 1)];
__device__ int g_list[4 * EE];
__device__ int g_cur[4 * NN];

// ---------------- helpers ----------------
__device__ __forceinline__ uint32_t smem_u32(const void* p) {
    uint32_t a;
    asm("{ .reg .u64 t; cvta.to.shared.u64 t, %1; cvt.u32.u64 %0, t; }" : "=r"(a) : "l"(p));
    return a;
}
__device__ __forceinline__ void cp_async16(uint32_t dst, const void* src, int sz) {
    asm volatile("cp.async.cg.shared.global [%0], [%1], 16, %2;"
                 :: "r"(dst), "l"(src), "r"(sz) : "memory");
}
__device__ __forceinline__ void cp_commit() { asm volatile("cp.async.commit_group;" ::: "memory"); }
template <int Nw>
__device__ __forceinline__ void cp_wait() { asm volatile("cp.async.wait_group %0;" ::"n"(Nw) : "memory"); }

__device__ __forceinline__ uint32_t pack_bf2(__nv_bfloat16 a, __nv_bfloat16 b) {
    __nv_bfloat162 t = __halves2bfloat162(a, b);
    return *(uint32_t*)&t;
}

// ---------------- CSR build ----------------
__global__ void zero_int(int* __restrict__ p, int n) {
    int i = blockIdx.x * blockDim.x + threadIdx.x;
    if (i < n) p[i] = 0;
}

__global__ void hist_k(const int* __restrict__ e0, const int* __restrict__ e1,
                       const int* __restrict__ e2, const int* __restrict__ e3) {
    int t = blockIdx.y;
    const int* e = (t == 0) ? e0 : (t == 1) ? e1 : (t == 2) ? e2 : e3;
    int i = blockIdx.x * blockDim.x + threadIdx.x;
    if (i < EE) atomicAdd(&g_cur[t * NN + e[EE + i]], 1);
}

__global__ void __launch_bounds__(1024) scan_k() {
    int t = blockIdx.x;
    const int C = (NN + 1023) / 1024;
    __shared__ int part[1024];
    int start = threadIdx.x * C;
    int s = 0;
    for (int i = 0; i < C; i++) {
        int j = start + i;
        if (j < NN) s += g_cur[t * NN + j];
    }
    part[threadIdx.x] = s;
    __syncthreads();
    if (threadIdx.x == 0) {
        int a = 0;
        for (int i = 0; i < 1024; i++) { int v = part[i]; part[i] = a; a += v; }
    }
    __syncthreads();
    int a = part[threadIdx.x];
    for (int i = 0; i < C; i++) {
        int j = start + i;
        if (j < NN) {
            g_off[t * (NN + 1) + j] = a;
            a += g_cur[t * NN + j];
        }
    }
    if (threadIdx.x == 0) g_off[t * (NN + 1) + NN] = EE;
}

__global__ void copy_cursor() {
    int i = blockIdx.x * blockDim.x + threadIdx.x;
    if (i < 4 * NN) {
        int t = i / NN, j = i - t * NN;
        g_cur[i] = g_off[t * (NN + 1) + j];
    }
}

__global__ void fill_k(const int* __restrict__ e0, const int* __restrict__ e1,
                       const int* __restrict__ e2, const int* __restrict__ e3) {
    int t = blockIdx.y;
    const int* e = (t == 0) ? e0 : (t == 1) ? e1 : (t == 2) ? e2 : e3;
    int i = blockIdx.x * blockDim.x + threadIdx.x;
    if (i < EE) {
        int d = e[EE + i];
        int p = atomicAdd(&g_cur[t * NN + d], 1);
        g_list[t * EE + p] = e[i];
    }
}

// ---------------- CSR gather-aggregate ----------------
template <int VP>
__global__ void __launch_bounds__(256) aggregate_k(const float* __restrict__ h) {
    const int D = 32 * VP, KA = 10 * D;
    int wid = threadIdx.x >> 5, lane = threadIdx.x & 31;
    int n = blockIdx.x * 8 + wid;
    int t = blockIdx.y;
    if (n >= NN) return;
    int beg = g_off[t * (NN + 1) + n], end = g_off[t * (NN + 1) + n + 1];
    float acc[VP];
#pragma unroll
    for (int i = 0; i < VP; i++) acc[i] = 0.f;
    const int* lst = g_list + (size_t)t * EE;
    for (int e = beg; e < end; e++) {
        int s = __ldg(&lst[e]);
        const float4* src = (const float4*)(h + (size_t)s * D + lane * VP);
#pragma unroll
        for (int q = 0; q < VP / 4; q++) {
            float4 v = __ldg(&src[q]);
            acc[q * 4 + 0] += v.x; acc[q * 4 + 1] += v.y;
            acc[q * 4 + 2] += v.z; acc[q * 4 + 3] += v.w;
        }
    }
    float inv = 1.0f / fmaxf((float)(end - beg), 1.0f);
    uint32_t hw[VP / 2], lw[VP / 2];
#pragma unroll
    for (int i = 0; i < VP / 2; i++) {
        float v0 = acc[2 * i] * inv, v1 = acc[2 * i + 1] * inv;
        __nv_bfloat16 h0 = __float2bfloat16_rn(v0);
        __nv_bfloat16 h1 = __float2bfloat16_rn(v1);
        hw[i] = pack_bf2(h0, h1);
        lw[i] = pack_bf2(__float2bfloat16_rn(v0 - __bfloat162float(h0)),
                         __float2bfloat16_rn(v1 - __bfloat162float(h1)));
    }
    __nv_bfloat16* dhi = g_Abf + (size_t)n * KA + t * D + lane * VP;
    __nv_bfloat16* dlo = dhi + 5 * D;
    if (VP == 8) {
        *(uint4*)dhi = make_uint4(hw[0], hw[1], hw[2], hw[3]);
        *(uint4*)dlo = make_uint4(lw[0], lw[1], lw[2], lw[3]);
    } else {
        *(uint2*)dhi = make_uint2(hw[0], hw[1]);
        *(uint2*)dlo = make_uint2(lw[0], lw[1]);
    }
}

// self part for GNN layers: columns [4D,5D) hi, [9D,10D) lo
__global__ void convert_self(const float* __restrict__ h, int D) {
    int r4 = D / 4;
    long i = (long)blockIdx.x * blockDim.x + threadIdx.x;
    if (i >= (long)NN * r4) return;
    int n = (int)(i / r4);
    int c = (int)(i % r4) * 4;
    float4 v = *(const float4*)&h[(size_t)n * D + c];
    int KA = 10 * D;
    __nv_bfloat16 hx = __float2bfloat16_rn(v.x);
    __nv_bfloat16 hy = __float2bfloat16_rn(v.y);
    __nv_bfloat16 hz = __float2bfloat16_rn(v.z);
    __nv_bfloat16 hw4 = __float2bfloat16_rn(v.w);
    uint2 hv = make_uint2(pack_bf2(hx, hy), pack_bf2(hz, hw4));
    uint2 lv = make_uint2(
        pack_bf2(__float2bfloat16_rn(v.x - __bfloat162float(hx)),
                 __float2bfloat16_rn(v.y - __bfloat162float(hy))),
        pack_bf2(__float2bfloat16_rn(v.z - __bfloat162float(hz)),
                 __float2bfloat16_rn(v.w - __bfloat162float(hw4))));
    *(uint2*)(g_Abf + (size_t)n * KA + 4 * D + c) = hv;
    *(uint2*)(g_Abf + (size_t)n * KA + 9 * D + c) = lv;
}

// full-row hi/lo convert for tail GEMMs: out row = [hi(K) | lo(K)]
__global__ void convert_hl(const float* __restrict__ X, int K) {
    int r4 = K / 4;
    long i = (long)blockIdx.x * blockDim.x + threadIdx.x;
    if (i >= (long)NN * r4) return;
    int n = (int)(i / r4);
    int c = (int)(i % r4) * 4;
    float4 v = *(const float4*)&X[(size_t)n * K + c];
    __nv_bfloat16 hx = __float2bfloat16_rn(v.x);
    __nv_bfloat16 hy = __float2bfloat16_rn(v.y);
    __nv_bfloat16 hz = __float2bfloat16_rn(v.z);
    __nv_bfloat16 hw4 = __float2bfloat16_rn(v.w);
    uint2 hv = make_uint2(pack_bf2(hx, hy), pack_bf2(hz, hw4));
    uint2 lv = make_uint2(
        pack_bf2(__float2bfloat16_rn(v.x - __bfloat162float(hx)),
                 __float2bfloat16_rn(v.y - __bfloat162float(hy))),
        pack_bf2(__float2bfloat16_rn(v.z - __bfloat162float(hz)),
                 __float2bfloat16_rn(v.w - __bfloat162float(hw4))));
    *(uint2*)(g_Abf + (size_t)n * 2 * K + c) = hv;
    *(uint2*)(g_Abf + (size_t)n * 2 * K + K + c) = lv;
}

// tail weight build: W [K, Nout] fp32 -> g_Bt[128][3K] = [hi; lo; hi], zero rows n>=Nout
__global__ void build_W(const float* __restrict__ W, int K, int Nout) {
    long i = (long)blockIdx.x * blockDim.x + threadIdx.x;
    if (i >= (long)128 * K) return;
    int n = (int)(i / K), k = (int)(i % K);
    float v = (n < Nout) ? W[(size_t)k * Nout + n] : 0.f;
    __nv_bfloat16 hi = __float2bfloat16_rn(v);
    __nv_bfloat16 lo = __float2bfloat16_rn(v - __bfloat162float(hi));
    g_Bt[(size_t)n * 3 * K + k] = hi;
    g_Bt[(size_t)n * 3 * K + K + k] = lo;
    g_Bt[(size_t)n * 3 * K + 2 * K + k] = hi;
}

// ---------------- bf16 mma.sync GEMM (generic) ----------------
// grid = (colBlocks, rowBlocks). Chunk i schedule: pairs (Bhi_j, Blo_j) then Alo*Bhi.
#define BKC 32
__global__ void __launch_bounds__(256, 2)
mma_gemm(const __nv_bfloat16* __restrict__ A, int KA,
         const __nv_bfloat16* __restrict__ B, int K3,
         const float* __restrict__ bias, float* __restrict__ C,
         int ldc, int Nout, int NCb, int relu) {
    __shared__ __nv_bfloat16 As[2][128][40];
    __shared__ __nv_bfloat16 Bs[2][128][40];
    int tid = threadIdx.x;
    int wid = tid >> 5, lane = tid & 31;
    int t4 = lane >> 2, tq = lane & 3;
    int warp_m = wid & 3;
    int warp_n = wid >> 2;
    int colC = blockIdx.x * 128;
    int rowBase = blockIdx.y * 128;
    int m0 = warp_m * 32, n0 = warp_n * 64;
    int NC = 3 * NCb;

    float acc[2][8][4];
#pragma unroll
    for (int i = 0; i < 2; i++)
#pragma unroll
        for (int j = 0; j < 8; j++)
#pragma unroll
            for (int q = 0; q < 4; q++) acc[i][j][q] = 0.f;

    auto issue = [&](int it, int s) {
        int cc = (it < 2 * NCb) ? ((it >> 1) + (it & 1) * NCb) : it;
        int ac = (cc < NCb) ? cc : cc - NCb;
#pragma unroll
        for (int i = 0; i < 2; i++) {
            int u = tid + i * 256;
            int r = u >> 2, q = u & 3;
            int gr = rowBase + r;
            const __nv_bfloat16* srcA = A + (size_t)gr * KA + ac * BKC + q * 8;
            cp_async16(smem_u32(&As[s][r][q * 8]), srcA, gr < NN ? 16 : 0);
            const __nv_bfloat16* srcB = B + (size_t)(colC + r) * K3 + cc * BKC + q * 8;
            cp_async16(smem_u32(&Bs[s][r][q * 8]), srcB, 16);
        }
        cp_commit();
    };

    issue(0, 0);

    for (int c = 0; c < NC; c++) {
        int s = c & 1;
        if (c + 1 < NC) {
            issue(c + 1, s ^ 1);
            cp_wait<1>();
        } else {
            cp_wait<0>();
        }
        __syncthreads();

        const __nv_bfloat16(*as)[40] = As[s];
        const __nv_bfloat16(*bs)[40] = Bs[s];
#pragma unroll
        for (int ks = 0; ks < 2; ks++) {
            uint32_t a[2][4], b[8][2];
#pragma unroll
            for (int im = 0; im < 2; im++) {
                int rm = m0 + im * 16 + t4;
                int kc = ks * 16 + tq * 2;
                a[im][0] = *(const uint32_t*)&as[rm][kc];
                a[im][1] = *(const uint32_t*)&as[rm + 8][kc];
                a[im][2] = *(const uint32_t*)&as[rm][kc + 8];
                a[im][3] = *(const uint32_t*)&as[rm + 8][kc + 8];
            }
#pragma unroll
            for (int in = 0; in < 8; in++) {
                int rn = n0 + in * 8 + t4;
                int kc = ks * 16 + tq * 2;
                b[in][0] = *(const uint32_t*)&bs[rn][kc];
                b[in][1] = *(const uint32_t*)&bs[rn][kc + 8];
            }
#pragma unroll
            for (int im = 0; im < 2; im++)
#pragma unroll
                for (int in = 0; in < 8; in++) {
                    asm volatile(
                        "mma.sync.aligned.m16n8k16.row.col.f32.bf16.bf16.f32 "
                        "{%0,%1,%2,%3}, {%4,%5,%6,%7}, {%8,%9}, {%0,%1,%2,%3};"
                        : "+f"(acc[im][in][0]), "+f"(acc[im][in][1]),
                          "+f"(acc[im][in][2]), "+f"(acc[im][in][3])
                        : "r"(a[im][0]), "r"(a[im][1]), "r"(a[im][2]), "r"(a[im][3]),
                          "r"(b[in][0]), "r"(b[in][1]));
                }
        }
        __syncthreads();
    }

#pragma unroll
    for (int im = 0; im < 2; im++) {
        int gr0 = rowBase + m0 + im * 16 + t4;
#pragma unroll
        for (int in = 0; in < 8; in++) {
            int col = colC + n0 + in * 8 + tq * 2;
            if (col >= Nout) continue;
            float bx = bias[col], by = bias[col + 1];
            float2 v0 = make_float2(acc[im][in][0] + bx, acc[im][in][1] + by);
            float2 v1 = make_float2(acc[im][in][2] + bx, acc[im][in][3] + by);
            if (relu) {
                v0.x = fmaxf(v0.x, 0.f); v0.y = fmaxf(v0.y, 0.f);
                v1.x = fmaxf(v1.x, 0.f); v1.y = fmaxf(v1.y, 0.f);
            }
            if (gr0 < NN) *(float2*)&C[(size_t)gr0 * ldc + col] = v0;
            if (gr0 + 8 < NN) *(float2*)&C[(size_t)(gr0 + 8) * ldc + col] = v1;
        }
    }
}

// ---------------- misc ----------------
__global__ void zero_buf(float* __restrict__ p, long n) {
    long i = (long)blockIdx.x * blockDim.x + threadIdx.x;
    if (i < n) p[i] = 0.0f;
}

__global__ void build_Bbf(const float* __restrict__ Wl, const float* __restrict__ Wr,
                          const float* __restrict__ bl, int D) {
    long i = (long)blockIdx.x * blockDim.x + threadIdx.x;
    long total = (long)5 * D * 256;
    if (i >= total) return;
    int k = (int)(i / 256), n = (int)(i % 256);
    float v;
    if (k < 4 * D) {
        v = Wl[(size_t)k * 256 + n];
    } else {
        int kk = k - 4 * D;
        v = Wr[(size_t)kk * 256 + n] + Wr[((size_t)D + kk) * 256 + n] +
            Wr[((size_t)2 * D + kk) * 256 + n] + Wr[((size_t)3 * D + kk) * 256 + n];
    }
    int K3 = 15 * D;
    __nv_bfloat16 hi = __float2bfloat16_rn(v);
    __nv_bfloat16 lo = __float2bfloat16_rn(v - __bfloat162float(hi));
    g_Bbf[(size_t)n * K3 + k] = hi;
    g_Bbf[(size_t)n * K3 + 5 * D + k] = lo;
    g_Bbf[(size_t)n * K3 + 10 * D + k] = hi;
    if (i < 256) g_bias[i] = bl[i] + bl[256 + i] + bl[512 + i] + bl[768 + i];
}

// ---------------- tail kernels ----------------
__global__ void __launch_bounds__(256) pool_gather(const float* __restrict__ hin,
                                                   float* __restrict__ hout) {
    int wid = threadIdx.x >> 5, lane = threadIdx.x & 31;
    int n = blockIdx.x * 8 + wid;
    if (n >= NN) return;
    int beg = g_off[n], end = g_off[n + 1];
    float4 acc = *(const float4*)&hin[(size_t)n * 128 + lane * 4];
    for (int e = beg; e < end; e++) {
        int s = __ldg(&g_list[e]);
        float4 v = __ldg((const float4*)&hin[(size_t)s * 128 + lane * 4]);
        acc.x += v.x; acc.y += v.y; acc.z += v.z; acc.w += v.w;
    }
    float inv = 1.0f / fmaxf((float)(end - beg), 1.0f);
    acc.x *= inv; acc.y *= inv; acc.z *= inv; acc.w *= inv;
    *(float4*)&hout[(size_t)n * 128 + lane * 4] = acc;
}

__global__ void layernorm_k(const float* __restrict__ in, float* __restrict__ out,
                            const float* __restrict__ g, const float* __restrict__ b) {
    int row = blockIdx.x * 8 + (threadIdx.x >> 5);
    int lane = threadIdx.x & 31;
    if (row >= NN) return;
    float4 v = *(const float4*)&in[(size_t)row * 128 + lane * 4];
    float s = v.x + v.y + v.z + v.w;
    float q = v.x * v.x + v.y * v.y + v.z * v.z + v.w * v.w;
#pragma unroll
    for (int o = 16; o; o >>= 1) {
        s += __shfl_xor_sync(0xffffffffu, s, o);
        q += __shfl_xor_sync(0xffffffffu, q, o);
    }
    float mu = s * (1.0f / 128.0f);
    float var = q * (1.0f / 128.0f) - mu * mu;
    float r = rsqrtf(var + 1e-5f);
    float4 gg = *(const float4*)&g[lane * 4];
    float4 bb = *(const float4*)&b[lane * 4];
    float4 o4;
    o4.x = (v.x - mu) * r * gg.x + bb.x;
    o4.y = (v.y - mu) * r * gg.y + bb.y;
    o4.z = (v.z - mu) * r * gg.z + bb.z;
    o4.w = (v.w - mu) * r * gg.w + bb.w;
    *(float4*)&out[(size_t)row * 128 + lane * 4] = o4;
}

__global__ void bn_stats(const float* __restrict__ z) {
    __shared__ float ssum[256], ssq[256];
    int c = threadIdx.x & 63;
    int sub = threadIdx.x >> 6;
    float s = 0.f, q = 0.f;
    for (long r = (long)blockIdx.x * 4 + sub; r < NN; r += (long)gridDim.x * 4) {
        float v = z[r * 64 + c];
        s += v; q += v * v;
    }
    ssum[threadIdx.x] = s; ssq[threadIdx.x] = q;
    __syncthreads();
    if (sub == 0) {
        s = ssum[c] + ssum[64 + c] + ssum[128 + c] + ssum[192 + c];
        q = ssq[c] + ssq[64 + c] + ssq[128 + c] + ssq[192 + c];
        atomicAdd(&g_stats[c], s);
        atomicAdd(&g_stats[64 + c], q);
    }
}

__global__ void finalize_k(const float* __restrict__ z, const float* __restrict__ bn_g,
                           const float* __restrict__ bn_b, const float* __restrict__ cW2,
                           const float* __restrict__ cb2, float* __restrict__ out) {
    __shared__ float w[448], smu[64], sr[64], sg[64], sb[64], sb2[7];
    int tid = threadIdx.x;
    for (int i = tid; i < 448; i += blockDim.x) w[i] = cW2[i];
    if (tid < 64) {
        float mu = g_stats[tid] / (float)NN;
        float var = g_stats[64 + tid] / (float)NN - mu * mu;
        smu[tid] = mu;
        sr[tid] = rsqrtf(var + 1e-5f);
        sg[tid] = bn_g[tid];
        sb[tid] = bn_b[tid];
    }
    if (tid < 7) sb2[tid] = cb2[tid];
    __syncthreads();
    int row = blockIdx.x * blockDim.x + tid;
    if (row >= NN) return;
    float logits[7];
#pragma unroll
    for (int j = 0; j < 7; j++) logits[j] = sb2[j];
    for (int c = 0; c < 64; c += 4) {
        float4 v4 = *(const float4*)&z[(size_t)row * 64 + c];
        float vv[4] = {v4.x, v4.y, v4.z, v4.w};
#pragma unroll
        for (int u = 0; u < 4; u++) {
            int cc = c + u;
            float v = (vv[u] - smu[cc]) * sr[cc] * sg[cc] + sb[cc];
#pragma unroll
            for (int j = 0; j < 7; j++) logits[j] += v * w[cc * 7 + j];
        }
    }
    float m = logits[0];
#pragma unroll
    for (int j = 1; j < 7; j++) m = fmaxf(m, logits[j]);
    float ssum = 0.f;
#pragma unroll
    for (int j = 0; j < 7; j++) { logits[j] = expf(logits[j] - m); ssum += logits[j]; }
    float inv = 1.0f / ssum;
#pragma unroll
    for (int j = 0; j < 7; j++) out[(size_t)row * 7 + j] = logits[j] * inv;
}

// ---------------- host launcher ----------------
static inline int cdiv(long a, int b) { return (int)((a + b - 1) / b); }

extern "C" void kernel_launch(void* const* d_in, const int* in_sizes, int n_in,
                              void* d_out, int out_size) {
    const float* x = (const float*)d_in[0];
    const int* e0 = (const int*)d_in[1];
    const int* e1 = (const int*)d_in[2];
    const int* e2 = (const int*)d_in[3];
    const int* e3 = (const int*)d_in[4];
    const float* Wl0 = (const float*)d_in[5];
    const float* bl0 = (const float*)d_in[6];
    const float* Wr0 = (const float*)d_in[7];
    const float* Wl = (const float*)d_in[8];
    const float* bl = (const float*)d_in[9];
    const float* Wr = (const float*)d_in[10];
    const float* lin_W = (const float*)d_in[11];
    const float* lin_b = (const float*)d_in[12];
    const float* norm_g = (const float*)d_in[13];
    const float* norm_b = (const float*)d_in[14];
    const float* pW1 = (const float*)d_in[15];
    const float* pb1 = (const float*)d_in[16];
    const float* pln_g = (const float*)d_in[17];
    const float* pln_b = (const float*)d_in[18];
    const float* pW2 = (const float*)d_in[19];
    const float* pb2 = (const float*)d_in[20];
    const float* cW1 = (const float*)d_in[21];
    const float* cb1 = (const float*)d_in[22];
    const float* bn_g = (const float*)d_in[23];
    const float* bn_b = (const float*)d_in[24];
    const float* cW2 = (const float*)d_in[25];
    const float* cb2 = (const float*)d_in[26];
    float* out = (float*)d_out;

    float *pm, *pbias, *ph, *ph2, *pstats;
    __nv_bfloat16 *pAbf, *pBbf, *pBt;
    int* pcur;
    cudaGetSymbolAddress((void**)&pm, g_m);
    cudaGetSymbolAddress((void**)&pAbf, g_Abf);
    cudaGetSymbolAddress((void**)&pBbf, g_Bbf);
    cudaGetSymbolAddress((void**)&pBt, g_Bt);
    cudaGetSymbolAddress((void**)&pbias, g_bias);
    cudaGetSymbolAddress((void**)&ph, g_h);
    cudaGetSymbolAddress((void**)&ph2, g_h2);
    cudaGetSymbolAddress((void**)&pstats, g_stats);
    cudaGetSymbolAddress((void**)&pcur, g_cur);

    const int T = 256;
    const int RB = cdiv(NN, 128);               // 391 row blocks
    const dim3 MAIN_GRID(2, RB);                // col-major adjacency for L2 A reuse
    const dim3 TAIL_GRID(1, RB);
    const dim3 AGG_GRID(cdiv(NN, 8), 4);
    const dim3 EDGE_GRID(cdiv(EE, T), 4);

    // ---- CSR build ----
    zero_int<<<cdiv(4L * NN, T), T>>>(pcur, 4 * NN);
    hist_k<<<EDGE_GRID, T>>>(e0, e1, e2, e3);
    scan_k<<<4, 1024>>>();
    copy_cursor<<<cdiv(4L * NN, T), T>>>();
    fill_k<<<EDGE_GRID, T>>>(e0, e1, e2, e3);

    // ---- Layer 0 (D = 128) ----
    build_Bbf<<<cdiv(5L * 128 * 256, T), T>>>(Wl0, Wr0, bl0, 128);
    aggregate_k<4><<<AGG_GRID, 256>>>(x);
    convert_self<<<cdiv((long)NN * 32, T), T>>>(x, 128);
    mma_gemm<<<MAIN_GRID, 256>>>(pAbf, 1280, pBbf, 1920, pbias, ph, 256, 256, 20, 1);

    // ---- Layers 1, 2 (D = 256) ----
    float* hin = ph;
    float* hout = ph2;
    for (int l = 0; l < 2; l++) {
        build_Bbf<<<cdiv(5L * 256 * 256, T), T>>>(Wl + (size_t)l * 4 * 256 * 256,
                                                  Wr + (size_t)l * 4 * 256 * 256,
                                                  bl + (size_t)l * 4 * 256, 256);
        aggregate_k<8><<<AGG_GRID, 256>>>(hin);
        convert_self<<<cdiv((long)NN * 64, T), T>>>(hin, 256);
        mma_gemm<<<MAIN_GRID, 256>>>(pAbf, 2560, pBbf, 3840, pbias, hout, 256, 256, 40, 1);
        float* tmp = hin; hin = hout; hout = tmp;
    }
    // GNN output in hin == ph  (L=2 even swaps)

    // ---- lin: [N,256]@[256,128]+b (bf16x3) ----
    convert_hl<<<cdiv((long)NN * 64, T), T>>>(hin, 256);
    build_W<<<cdiv(128L * 256, T), T>>>(lin_W, 256, 128);
    mma_gemm<<<TAIL_GRID, 256>>>(pAbf, 512, pBt, 768, lin_b, ph2, 128, 128, 8, 0);

    // onset pooling (relation 0 CSR)
    pool_gather<<<cdiv(NN, 8), 256>>>(ph2, pm);
    layernorm_k<<<cdiv(NN, 8), 256>>>(pm, ph, norm_g, norm_b);

    // pool_mlp: relu(h@pW1+pb1) -> LN -> @pW2+pb2
    convert_hl<<<cdiv((long)NN * 32, T), T>>>(ph, 128);
    build_W<<<cdiv(128L * 128, T), T>>>(pW1, 128, 128);
    mma_gemm<<<TAIL_GRID, 256>>>(pAbf, 256, pBt, 384, pb1, ph2, 128, 128, 4, 1);
    layernorm_k<<<cdiv(NN, 8), 256>>>(ph2, ph, pln_g, pln_b);
    convert_hl<<<cdiv((long)NN * 32, T), T>>>(ph, 128);
    build_W<<<cdiv(128L * 128, T), T>>>(pW2, 128, 128);
    mma_gemm<<<TAIL_GRID, 256>>>(pAbf, 256, pBt, 384, pb2, ph2, 128, 128, 4, 0);

    // clf first layer + relu (N=64)
    convert_hl<<<cdiv((long)NN * 32, T), T>>>(ph2, 128);
    build_W<<<cdiv(128L * 128, T), T>>>(cW1, 128, 64);
    mma_gemm<<<TAIL_GRID, 256>>>(pAbf, 256, pBt, 384, cb1, ph, 64, 64, 4, 1);

    zero_buf<<<1, 128>>>(pstats, 128);
    bn_stats<<<512, 256>>>(ph);
    finalize_k<<<cdiv(NN, 256), 256>>>(ph, bn_g, bn_b, cW2, cb2, out);
}

// round 6
// speedup vs baseline: 2.3132x; 1.0532x over previous
#include <cuda_runtime.h>
#include <cuda_bf16.h>
#include <cstdint>

#define NN 50000
#define EE 500000

// ---------------- scratch (static device globals; no runtime allocation) ----------------
__device__ __align__(16) float g_m[(size_t)NN * 128];               // pooling temp
__device__ __align__(16) __nv_bfloat16 g_AbfA[(size_t)NN * 2560];   // ping A' buffer
__device__ __align__(16) __nv_bfloat16 g_AbfB[(size_t)NN * 2560];   // pong A' buffer
__device__ __align__(16) __nv_bfloat16 g_Bbf[(size_t)256 * 3840];   // main B' = [Bhi; Blo; Bhi]
__device__ __align__(16) __nv_bfloat16 g_Bt[(size_t)128 * 768];     // tail B'
__device__ __align__(16) float g_bias[256];
__device__ __align__(16) float g_h[(size_t)NN * 256];
__device__ __align__(16) float g_h2[(size_t)NN * 256];
__device__ __align__(16) float g_stats[128];
// CSR
__device__ int g_off[4 * (NN + 1)];
__device__ int g_list[4 * EE];
__device__ int g_cur[4 * NN];

// ---------------- helpers ----------------
__device__ __forceinline__ uint32_t smem_u32(const void* p) {
    uint32_t a;
    asm("{ .reg .u64 t; cvta.to.shared.u64 t, %1; cvt.u32.u64 %0, t; }" : "=r"(a) : "l"(p));
    return a;
}
__device__ __forceinline__ void cp_async16(uint32_t dst, const void* src, int sz) {
    asm volatile("cp.async.cg.shared.global [%0], [%1], 16, %2;"
                 :: "r"(dst), "l"(src), "r"(sz) : "memory");
}
__device__ __forceinline__ void cp_commit() { asm volatile("cp.async.commit_group;" ::: "memory"); }
template <int Nw>
__device__ __forceinline__ void cp_wait() { asm volatile("cp.async.wait_group %0;" ::"n"(Nw) : "memory"); }

__device__ __forceinline__ uint32_t pack_bf2(__nv_bfloat16 a, __nv_bfloat16 b) {
    __nv_bfloat162 t = __halves2bfloat162(a, b);
    return *(uint32_t*)&t;
}
__device__ __forceinline__ void hl_pack(float x, float y, uint32_t& hi, uint32_t& lo) {
    __nv_bfloat16 hx = __float2bfloat16_rn(x);
    __nv_bfloat16 hy = __float2bfloat16_rn(y);
    hi = pack_bf2(hx, hy);
    lo = pack_bf2(__float2bfloat16_rn(x - __bfloat162float(hx)),
                  __float2bfloat16_rn(y - __bfloat162float(hy)));
}
__device__ __forceinline__ void ldsm4(uint32_t& r0, uint32_t& r1, uint32_t& r2, uint32_t& r3,
                                      uint32_t addr) {
    asm volatile("ldmatrix.sync.aligned.m8n8.x4.shared.b16 {%0,%1,%2,%3}, [%4];"
                 : "=r"(r0), "=r"(r1), "=r"(r2), "=r"(r3) : "r"(addr));
}

// ---------------- CSR build ----------------
__global__ void zero_int(int* __restrict__ p, int n) {
    int i = blockIdx.x * blockDim.x + threadIdx.x;
    if (i < n) p[i] = 0;
}
__global__ void hist_k(const int* __restrict__ e0, const int* __restrict__ e1,
                       const int* __restrict__ e2, const int* __restrict__ e3) {
    int t = blockIdx.y;
    const int* e = (t == 0) ? e0 : (t == 1) ? e1 : (t == 2) ? e2 : e3;
    int i = blockIdx.x * blockDim.x + threadIdx.x;
    if (i < EE) atomicAdd(&g_cur[t * NN + e[EE + i]], 1);
}
__global__ void __launch_bounds__(1024) scan_k() {
    int t = blockIdx.x;
    const int C = (NN + 1023) / 1024;
    __shared__ int part[1024];
    int start = threadIdx.x * C;
    int s = 0;
    for (int i = 0; i < C; i++) {
        int j = start + i;
        if (j < NN) s += g_cur[t * NN + j];
    }
    part[threadIdx.x] = s;
    __syncthreads();
    if (threadIdx.x == 0) {
        int a = 0;
        for (int i = 0; i < 1024; i++) { int v = part[i]; part[i] = a; a += v; }
    }
    __syncthreads();
    int a = part[threadIdx.x];
    for (int i = 0; i < C; i++) {
        int j = start + i;
        if (j < NN) {
            g_off[t * (NN + 1) + j] = a;
            a += g_cur[t * NN + j];
        }
    }
    if (threadIdx.x == 0) g_off[t * (NN + 1) + NN] = EE;
}
__global__ void copy_cursor() {
    int i = blockIdx.x * blockDim.x + threadIdx.x;
    if (i < 4 * NN) {
        int t = i / NN, j = i - t * NN;
        g_cur[i] = g_off[t * (NN + 1) + j];
    }
}
__global__ void fill_k(const int* __restrict__ e0, const int* __restrict__ e1,
                       const int* __restrict__ e2, const int* __restrict__ e3) {
    int t = blockIdx.y;
    const int* e = (t == 0) ? e0 : (t == 1) ? e1 : (t == 2) ? e2 : e3;
    int i = blockIdx.x * blockDim.x + threadIdx.x;
    if (i < EE) {
        int d = e[EE + i];
        int p = atomicAdd(&g_cur[t * NN + d], 1);
        g_list[t * EE + p] = e[i];
    }
}

// ---------------- CSR gather-aggregate ----------------
template <int VP>
__global__ void __launch_bounds__(256) aggregate_k(const float* __restrict__ h,
                                                   __nv_bfloat16* __restrict__ dst) {
    const int D = 32 * VP, KA = 10 * D;
    int wid = threadIdx.x >> 5, lane = threadIdx.x & 31;
    int n = blockIdx.x * 8 + wid;
    int t = blockIdx.y;
    if (n >= NN) return;
    int beg = g_off[t * (NN + 1) + n], end = g_off[t * (NN + 1) + n + 1];
    float acc[VP];
#pragma unroll
    for (int i = 0; i < VP; i++) acc[i] = 0.f;
    const int* lst = g_list + (size_t)t * EE;
    for (int e = beg; e < end; e++) {
        int s = __ldg(&lst[e]);
        const float4* src = (const float4*)(h + (size_t)s * D + lane * VP);
#pragma unroll
        for (int q = 0; q < VP / 4; q++) {
            float4 v = __ldg(&src[q]);
            acc[q * 4 + 0] += v.x; acc[q * 4 + 1] += v.y;
            acc[q * 4 + 2] += v.z; acc[q * 4 + 3] += v.w;
        }
    }
    float inv = 1.0f / fmaxf((float)(end - beg), 1.0f);
    uint32_t hw[VP / 2], lw[VP / 2];
#pragma unroll
    for (int i = 0; i < VP / 2; i++)
        hl_pack(acc[2 * i] * inv, acc[2 * i + 1] * inv, hw[i], lw[i]);
    __nv_bfloat16* dhi = dst + (size_t)n * KA + t * D + lane * VP;
    __nv_bfloat16* dlo = dhi + 5 * D;
    if (VP == 8) {
        *(uint4*)dhi = make_uint4(hw[0], hw[1], hw[2], hw[3]);
        *(uint4*)dlo = make_uint4(lw[0], lw[1], lw[2], lw[3]);
    } else {
        *(uint2*)dhi = make_uint2(hw[0], hw[1]);
        *(uint2*)dlo = make_uint2(lw[0], lw[1]);
    }
}

// self part for layer 0 only (input x, D=128): hi at [4D,5D), lo at [9D,10D)
__global__ void convert_self(const float* __restrict__ h, __nv_bfloat16* __restrict__ dst) {
    const int D = 128, KA = 1280;
    long i = (long)blockIdx.x * blockDim.x + threadIdx.x;
    if (i >= (long)NN * 32) return;
    int n = (int)(i >> 5);
    int c = (int)(i & 31) * 4;
    float4 v = *(const float4*)&h[(size_t)n * D + c];
    uint32_t h0, l0, h1, l1;
    hl_pack(v.x, v.y, h0, l0);
    hl_pack(v.z, v.w, h1, l1);
    *(uint2*)(dst + (size_t)n * KA + 4 * D + c) = make_uint2(h0, h1);
    *(uint2*)(dst + (size_t)n * KA + 9 * D + c) = make_uint2(l0, l1);
}

// tail weight build: W [K, Nout] fp32 -> g_Bt[128][3K] = [hi; lo; hi]
__global__ void build_W(const float* __restrict__ W, int K, int Nout) {
    long i = (long)blockIdx.x * blockDim.x + threadIdx.x;
    if (i >= (long)128 * K) return;
    int n = (int)(i / K), k = (int)(i % K);
    float v = (n < Nout) ? W[(size_t)k * Nout + n] : 0.f;
    __nv_bfloat16 hi = __float2bfloat16_rn(v);
    __nv_bfloat16 lo = __float2bfloat16_rn(v - __bfloat162float(hi));
    g_Bt[(size_t)n * 3 * K + k] = hi;
    g_Bt[(size_t)n * 3 * K + K + k] = lo;
    g_Bt[(size_t)n * 3 * K + 2 * K + k] = hi;
}

__global__ void build_Bbf(const float* __restrict__ Wl, const float* __restrict__ Wr,
                          const float* __restrict__ bl, int D) {
    long i = (long)blockIdx.x * blockDim.x + threadIdx.x;
    long total = (long)5 * D * 256;
    if (i >= total) return;
    int k = (int)(i / 256), n = (int)(i % 256);
    float v;
    if (k < 4 * D) {
        v = Wl[(size_t)k * 256 + n];
    } else {
        int kk = k - 4 * D;
        v = Wr[(size_t)kk * 256 + n] + Wr[((size_t)D + kk) * 256 + n] +
            Wr[((size_t)2 * D + kk) * 256 + n] + Wr[((size_t)3 * D + kk) * 256 + n];
    }
    int K3 = 15 * D;
    __nv_bfloat16 hi = __float2bfloat16_rn(v);
    __nv_bfloat16 lo = __float2bfloat16_rn(v - __bfloat162float(hi));
    g_Bbf[(size_t)n * K3 + k] = hi;
    g_Bbf[(size_t)n * K3 + 5 * D + k] = lo;
    g_Bbf[(size_t)n * K3 + 10 * D + k] = hi;
    if (i < 256) g_bias[i] = bl[i] + bl[256 + i] + bl[512 + i] + bl[768 + i];
}

// ---------------- main GNN GEMM: CTA 128x256, warp 64x64, ldmatrix, 3-stage ----------------
// A' rows [hi(5D)|lo(5D)], B' = g_Bbf rows [n][15D]. Epilogue: relu(bias+acc) ->
// optional fp32 C (ldc 256) + bf16 hi/lo into Chl (hlStride, hiOff, loOff).
#define MST 3
#define STB 30720  // stage bytes: A 128*40*2 + B 256*40*2
__global__ void __launch_bounds__(256, 1)
mma_main(const __nv_bfloat16* __restrict__ A, int KA,
         const float* __restrict__ bias, float* __restrict__ Cf,
         __nv_bfloat16* __restrict__ Chl, int hlStride, int hiOff, int loOff, int NCb) {
    extern __shared__ char smem[];
    const uint32_t sb = smem_u32(smem);
    const int K3 = NCb * 96;
    const int NC = NCb * 3;
    int tid = threadIdx.x;
    int wid = tid >> 5, lane = tid & 31;
    int t4 = lane >> 2, tq = lane & 3;
    int m0 = (wid & 1) * 64, n0 = (wid >> 1) * 64;
    int rowBase = blockIdx.x * 128;

    float acc[4][8][4];
#pragma unroll
    for (int i = 0; i < 4; i++)
#pragma unroll
        for (int j = 0; j < 8; j++)
#pragma unroll
            for (int q = 0; q < 4; q++) acc[i][j][q] = 0.f;

    // loader indices
    int ar = tid >> 1, aq = tid & 1;            // A: 128 rows x 2 x 16B  -> 1 per thread? 128*64B/16 = 512 -> 2 per thread
    // A tile = 128 rows x 32 halves = 8192 halves = 512 x16B; 2 per thread
    // B tile = 256 rows x 32 halves = 1024 x16B; 4 per thread
    auto issue = [&](int it, int s) {
        int cc = (it < 2 * NCb) ? ((it >> 1) + (it & 1) * NCb) : it;
        int ac = (cc < NCb) ? cc : cc - NCb;
        uint32_t abase = sb + s * STB;
        uint32_t bbase = abase + 10240;
#pragma unroll
        for (int i = 0; i < 2; i++) {
            int u = tid + i * 256;
            int r = u >> 2, q = u & 3;
            int gr = rowBase + r;
            cp_async16(abase + r * 80 + q * 16,
                       A + (size_t)gr * KA + ac * 32 + q * 8, gr < NN ? 16 : 0);
        }
#pragma unroll
        for (int i = 0; i < 4; i++) {
            int u = tid + i * 256;
            int r = u >> 2, q = u & 3;
            cp_async16(bbase + r * 80 + q * 16,
                       g_Bbf + (size_t)r * K3 + cc * 32 + q * 8, 16);
        }
        cp_commit();
    };
    (void)ar; (void)aq;

    // ldmatrix lane offsets (bytes)
    uint32_t aOff = (uint32_t)((m0 + (lane & 15)) * 80 + (lane >> 4) * 16);
    uint32_t bOff = (uint32_t)((n0 + ((lane >> 4) << 3) + (lane & 7)) * 80 + ((lane >> 3) & 1) * 16);

    issue(0, 0);
    issue(1, 1);

    for (int it = 0; it < NC; it++) {
        int s = it - (it / MST) * MST;
        cp_wait<1>();
        __syncthreads();
        uint32_t abase = sb + s * STB;
        uint32_t bbase = abase + 10240;
#pragma unroll
        for (int ks = 0; ks < 2; ks++) {
            uint32_t a[4][4], b[4][4];
#pragma unroll
            for (int tm = 0; tm < 4; tm++)
                ldsm4(a[tm][0], a[tm][1], a[tm][2], a[tm][3],
                      abase + aOff + tm * 1280 + ks * 32);
#pragma unroll
            for (int tb = 0; tb < 4; tb++)
                ldsm4(b[tb][0], b[tb][1], b[tb][2], b[tb][3],
                      bbase + bOff + tb * 1280 + ks * 32);
#pragma unroll
            for (int tm = 0; tm < 4; tm++)
#pragma unroll
                for (int tn = 0; tn < 8; tn++) {
                    uint32_t b0 = b[tn >> 1][(tn & 1) * 2];
                    uint32_t b1 = b[tn >> 1][(tn & 1) * 2 + 1];
                    asm volatile(
                        "mma.sync.aligned.m16n8k16.row.col.f32.bf16.bf16.f32 "
                        "{%0,%1,%2,%3}, {%4,%5,%6,%7}, {%8,%9}, {%0,%1,%2,%3};"
                        : "+f"(acc[tm][tn][0]), "+f"(acc[tm][tn][1]),
                          "+f"(acc[tm][tn][2]), "+f"(acc[tm][tn][3])
                        : "r"(a[tm][0]), "r"(a[tm][1]), "r"(a[tm][2]), "r"(a[tm][3]),
                          "r"(b0), "r"(b1));
                }
        }
        __syncthreads();
        if (it + 2 < NC) issue(it + 2, (it + 2) - ((it + 2) / MST) * MST);
    }

    // epilogue
#pragma unroll
    for (int tm = 0; tm < 4; tm++) {
        int r0 = rowBase + m0 + tm * 16 + t4;
        int r1 = r0 + 8;
#pragma unroll
        for (int tn = 0; tn < 8; tn++) {
            int col = n0 + tn * 8 + tq * 2;
            float bx = bias[col], by = bias[col + 1];
            float v0x = fmaxf(acc[tm][tn][0] + bx, 0.f);
            float v0y = fmaxf(acc[tm][tn][1] + by, 0.f);
            float v1x = fmaxf(acc[tm][tn][2] + bx, 0.f);
            float v1y = fmaxf(acc[tm][tn][3] + by, 0.f);
            if (r0 < NN) {
                if (Cf) *(float2*)&Cf[(size_t)r0 * 256 + col] = make_float2(v0x, v0y);
                uint32_t hi, lo;
                hl_pack(v0x, v0y, hi, lo);
                *(uint32_t*)(Chl + (size_t)r0 * hlStride + hiOff + col) = hi;
                *(uint32_t*)(Chl + (size_t)r0 * hlStride + loOff + col) = lo;
            }
            if (r1 < NN) {
                if (Cf) *(float2*)&Cf[(size_t)r1 * 256 + col] = make_float2(v1x, v1y);
                uint32_t hi, lo;
                hl_pack(v1x, v1y, hi, lo);
                *(uint32_t*)(Chl + (size_t)r1 * hlStride + hiOff + col) = hi;
                *(uint32_t*)(Chl + (size_t)r1 * hlStride + loOff + col) = lo;
            }
        }
    }
}

// ---------------- generic tail bf16 GEMM (CTA 128x128, warp 32x64) ----------------
__global__ void __launch_bounds__(256, 2)
mma_gemm(const __nv_bfloat16* __restrict__ A, int KA,
         const __nv_bfloat16* __restrict__ B, int K3,
         const float* __restrict__ bias, float* __restrict__ Cf,
         int ldc, int Nout, int NCb, int relu,
         __nv_bfloat16* __restrict__ Chl, int hlStride) {
    __shared__ __nv_bfloat16 As[2][128][40];
    __shared__ __nv_bfloat16 Bs[2][128][40];
    int tid = threadIdx.x;
    int wid = tid >> 5, lane = tid & 31;
    int t4 = lane >> 2, tq = lane & 3;
    int warp_m = wid & 3;
    int warp_n = wid >> 2;
    int rowBase = blockIdx.y * 128;
    int m0 = warp_m * 32, n0 = warp_n * 64;
    int NC = 3 * NCb;

    float acc[2][8][4];
#pragma unroll
    for (int i = 0; i < 2; i++)
#pragma unroll
        for (int j = 0; j < 8; j++)
#pragma unroll
            for (int q = 0; q < 4; q++) acc[i][j][q] = 0.f;

    auto issue = [&](int it, int s) {
        int cc = (it < 2 * NCb) ? ((it >> 1) + (it & 1) * NCb) : it;
        int ac = (cc < NCb) ? cc : cc - NCb;
#pragma unroll
        for (int i = 0; i < 2; i++) {
            int u = tid + i * 256;
            int r = u >> 2, q = u & 3;
            int gr = rowBase + r;
            cp_async16(smem_u32(&As[s][r][q * 8]),
                       A + (size_t)gr * KA + ac * 32 + q * 8, gr < NN ? 16 : 0);
            cp_async16(smem_u32(&Bs[s][r][q * 8]),
                       B + (size_t)r * K3 + cc * 32 + q * 8, 16);
        }
        cp_commit();
    };

    issue(0, 0);

    for (int c = 0; c < NC; c++) {
        int s = c & 1;
        if (c + 1 < NC) {
            issue(c + 1, s ^ 1);
            cp_wait<1>();
        } else {
            cp_wait<0>();
        }
        __syncthreads();
        const __nv_bfloat16(*as)[40] = As[s];
        const __nv_bfloat16(*bs)[40] = Bs[s];
#pragma unroll
        for (int ks = 0; ks < 2; ks++) {
            uint32_t a[2][4], b[8][2];
#pragma unroll
            for (int im = 0; im < 2; im++) {
                int rm = m0 + im * 16 + t4;
                int kc = ks * 16 + tq * 2;
                a[im][0] = *(const uint32_t*)&as[rm][kc];
                a[im][1] = *(const uint32_t*)&as[rm + 8][kc];
                a[im][2] = *(const uint32_t*)&as[rm][kc + 8];
                a[im][3] = *(const uint32_t*)&as[rm + 8][kc + 8];
            }
#pragma unroll
            for (int in = 0; in < 8; in++) {
                int rn = n0 + in * 8 + t4;
                int kc = ks * 16 + tq * 2;
                b[in][0] = *(const uint32_t*)&bs[rn][kc];
                b[in][1] = *(const uint32_t*)&bs[rn][kc + 8];
            }
#pragma unroll
            for (int im = 0; im < 2; im++)
#pragma unroll
                for (int in = 0; in < 8; in++) {
                    asm volatile(
                        "mma.sync.aligned.m16n8k16.row.col.f32.bf16.bf16.f32 "
                        "{%0,%1,%2,%3}, {%4,%5,%6,%7}, {%8,%9}, {%0,%1,%2,%3};"
                        : "+f"(acc[im][in][0]), "+f"(acc[im][in][1]),
                          "+f"(acc[im][in][2]), "+f"(acc[im][in][3])
                        : "r"(a[im][0]), "r"(a[im][1]), "r"(a[im][2]), "r"(a[im][3]),
                          "r"(b[in][0]), "r"(b[in][1]));
                }
        }
        __syncthreads();
    }

#pragma unroll
    for (int im = 0; im < 2; im++) {
        int gr0 = rowBase + m0 + im * 16 + t4;
#pragma unroll
        for (int in = 0; in < 8; in++) {
            int col = n0 + in * 8 + tq * 2;
            if (col >= Nout) continue;
            float bx = bias[col], by = bias[col + 1];
            float v0x = acc[im][in][0] + bx, v0y = acc[im][in][1] + by;
            float v1x = acc[im][in][2] + bx, v1y = acc[im][in][3] + by;
            if (relu) {
                v0x = fmaxf(v0x, 0.f); v0y = fmaxf(v0y, 0.f);
                v1x = fmaxf(v1x, 0.f); v1y = fmaxf(v1y, 0.f);
            }
            if (gr0 < NN) {
                if (Cf) *(float2*)&Cf[(size_t)gr0 * ldc + col] = make_float2(v0x, v0y);
                if (Chl) {
                    uint32_t hi, lo;
                    hl_pack(v0x, v0y, hi, lo);
                    *(uint32_t*)(Chl + (size_t)gr0 * hlStride + col) = hi;
                    *(uint32_t*)(Chl + (size_t)gr0 * hlStride + (hlStride >> 1) + col) = lo;
                }
            }
            if (gr0 + 8 < NN) {
                if (Cf) *(float2*)&Cf[(size_t)(gr0 + 8) * ldc + col] = make_float2(v1x, v1y);
                if (Chl) {
                    uint32_t hi, lo;
                    hl_pack(v1x, v1y, hi, lo);
                    *(uint32_t*)(Chl + (size_t)(gr0 + 8) * hlStride + col) = hi;
                    *(uint32_t*)(Chl + (size_t)(gr0 + 8) * hlStride + (hlStride >> 1) + col) = lo;
                }
            }
        }
    }
}

// ---------------- tail kernels ----------------
__global__ void zero_buf(float* __restrict__ p, long n) {
    long i = (long)blockIdx.x * blockDim.x + threadIdx.x;
    if (i < n) p[i] = 0.0f;
}

__global__ void __launch_bounds__(256) pool_gather(const float* __restrict__ hin,
                                                   float* __restrict__ hout) {
    int wid = threadIdx.x >> 5, lane = threadIdx.x & 31;
    int n = blockIdx.x * 8 + wid;
    if (n >= NN) return;
    int beg = g_off[n], end = g_off[n + 1];
    float4 acc = *(const float4*)&hin[(size_t)n * 128 + lane * 4];
    for (int e = beg; e < end; e++) {
        int s = __ldg(&g_list[e]);
        float4 v = __ldg((const float4*)&hin[(size_t)s * 128 + lane * 4]);
        acc.x += v.x; acc.y += v.y; acc.z += v.z; acc.w += v.w;
    }
    float inv = 1.0f / fmaxf((float)(end - beg), 1.0f);
    acc.x *= inv; acc.y *= inv; acc.z *= inv; acc.w *= inv;
    *(float4*)&hout[(size_t)n * 128 + lane * 4] = acc;
}

// LayerNorm (dim 128) -> bf16 hi/lo output, row stride 256 halves
__global__ void layernorm_hl(const float* __restrict__ in, __nv_bfloat16* __restrict__ dst,
                             const float* __restrict__ g, const float* __restrict__ b) {
    int row = blockIdx.x * 8 + (threadIdx.x >> 5);
    int lane = threadIdx.x & 31;
    if (row >= NN) return;
    float4 v = *(const float4*)&in[(size_t)row * 128 + lane * 4];
    float s = v.x + v.y + v.z + v.w;
    float q = v.x * v.x + v.y * v.y + v.z * v.z + v.w * v.w;
#pragma unroll
    for (int o = 16; o; o >>= 1) {
        s += __shfl_xor_sync(0xffffffffu, s, o);
        q += __shfl_xor_sync(0xffffffffu, q, o);
    }
    float mu = s * (1.0f / 128.0f);
    float var = q * (1.0f / 128.0f) - mu * mu;
    float r = rsqrtf(var + 1e-5f);
    float4 gg = *(const float4*)&g[lane * 4];
    float4 bb = *(const float4*)&b[lane * 4];
    float ox = (v.x - mu) * r * gg.x + bb.x;
    float oy = (v.y - mu) * r * gg.y + bb.y;
    float oz = (v.z - mu) * r * gg.z + bb.z;
    float ow = (v.w - mu) * r * gg.w + bb.w;
    uint32_t h0, l0, h1, l1;
    hl_pack(ox, oy, h0, l0);
    hl_pack(oz, ow, h1, l1);
    *(uint2*)(dst + (size_t)row * 256 + lane * 4) = make_uint2(h0, h1);
    *(uint2*)(dst + (size_t)row * 256 + 128 + lane * 4) = make_uint2(l0, l1);
}

__global__ void bn_stats(const float* __restrict__ z) {
    __shared__ float ssum[256], ssq[256];
    int c = threadIdx.x & 63;
    int sub = threadIdx.x >> 6;
    float s = 0.f, q = 0.f;
    for (long r = (long)blockIdx.x * 4 + sub; r < NN; r += (long)gridDim.x * 4) {
        float v = z[r * 64 + c];
        s += v; q += v * v;
    }
    ssum[threadIdx.x] = s; ssq[threadIdx.x] = q;
    __syncthreads();
    if (sub == 0) {
        s = ssum[c] + ssum[64 + c] + ssum[128 + c] + ssum[192 + c];
        q = ssq[c] + ssq[64 + c] + ssq[128 + c] + ssq[192 + c];
        atomicAdd(&g_stats[c], s);
        atomicAdd(&g_stats[64 + c], q);
    }
}

__global__ void finalize_k(const float* __restrict__ z, const float* __restrict__ bn_g,
                           const float* __restrict__ bn_b, const float* __restrict__ cW2,
                           const float* __restrict__ cb2, float* __restrict__ out) {
    __shared__ float w[448], smu[64], sr[64], sg[64], sb[64], sb2[7];
    int tid = threadIdx.x;
    for (int i = tid; i < 448; i += blockDim.x) w[i] = cW2[i];
    if (tid < 64) {
        float mu = g_stats[tid] / (float)NN;
        float var = g_stats[64 + tid] / (float)NN - mu * mu;
        smu[tid] = mu;
        sr[tid] = rsqrtf(var + 1e-5f);
        sg[tid] = bn_g[tid];
        sb[tid] = bn_b[tid];
    }
    if (tid < 7) sb2[tid] = cb2[tid];
    __syncthreads();
    int row = blockIdx.x * blockDim.x + tid;
    if (row >= NN) return;
    float logits[7];
#pragma unroll
    for (int j = 0; j < 7; j++) logits[j] = sb2[j];
    for (int c = 0; c < 64; c += 4) {
        float4 v4 = *(const float4*)&z[(size_t)row * 64 + c];
        float vv[4] = {v4.x, v4.y, v4.z, v4.w};
#pragma unroll
        for (int u = 0; u < 4; u++) {
            int cc = c + u;
            float v = (vv[u] - smu[cc]) * sr[cc] * sg[cc] + sb[cc];
#pragma unroll
            for (int j = 0; j < 7; j++) logits[j] += v * w[cc * 7 + j];
        }
    }
    float m = logits[0];
#pragma unroll
    for (int j = 1; j < 7; j++) m = fmaxf(m, logits[j]);
    float ssum = 0.f;
#pragma unroll
    for (int j = 0; j < 7; j++) { logits[j] = expf(logits[j] - m); ssum += logits[j]; }
    float inv = 1.0f / ssum;
#pragma unroll
    for (int j = 0; j < 7; j++) out[(size_t)row * 7 + j] = logits[j] * inv;
}

// ---------------- host launcher ----------------
static inline int cdiv(long a, int b) { return (int)((a + b - 1) / b); }

extern "C" void kernel_launch(void* const* d_in, const int* in_sizes, int n_in,
                              void* d_out, int out_size) {
    const float* x = (const float*)d_in[0];
    const int* e0 = (const int*)d_in[1];
    const int* e1 = (const int*)d_in[2];
    const int* e2 = (const int*)d_in[3];
    const int* e3 = (const int*)d_in[4];
    const float* Wl0 = (const float*)d_in[5];
    const float* bl0 = (const float*)d_in[6];
    const float* Wr0 = (const float*)d_in[7];
    const float* Wl = (const float*)d_in[8];
    const float* bl = (const float*)d_in[9];
    const float* Wr = (const float*)d_in[10];
    const float* lin_W = (const float*)d_in[11];
    const float* lin_b = (const float*)d_in[12];
    const float* norm_g = (const float*)d_in[13];
    const float* norm_b = (const float*)d_in[14];
    const float* pW1 = (const float*)d_in[15];
    const float* pb1 = (const float*)d_in[16];
    const float* pln_g = (const float*)d_in[17];
    const float* pln_b = (const float*)d_in[18];
    const float* pW2 = (const float*)d_in[19];
    const float* pb2 = (const float*)d_in[20];
    const float* cW1 = (const float*)d_in[21];
    const float* cb1 = (const float*)d_in[22];
    const float* bn_g = (const float*)d_in[23];
    const float* bn_b = (const float*)d_in[24];
    const float* cW2 = (const float*)d_in[25];
    const float* cb2 = (const float*)d_in[26];
    float* out = (float*)d_out;

    float *pm, *pbias, *ph, *ph2, *pstats;
    __nv_bfloat16 *pA, *pB, *pBt;
    int* pcur;
    cudaGetSymbolAddress((void**)&pm, g_m);
    cudaGetSymbolAddress((void**)&pA, g_AbfA);
    cudaGetSymbolAddress((void**)&pB, g_AbfB);
    cudaGetSymbolAddress((void**)&pBt, g_Bt);
    cudaGetSymbolAddress((void**)&pbias, g_bias);
    cudaGetSymbolAddress((void**)&ph, g_h);
    cudaGetSymbolAddress((void**)&ph2, g_h2);
    cudaGetSymbolAddress((void**)&pstats, g_stats);
    cudaGetSymbolAddress((void**)&pcur, g_cur);

    static bool attr_set = false;
    if (!attr_set) {
        cudaFuncSetAttribute(mma_main, cudaFuncAttributeMaxDynamicSharedMemorySize, MST * STB);
        attr_set = true;
    }

    const int T = 256;
    const int RB = cdiv(NN, 128);
    const dim3 TAIL_GRID(1, RB);
    const dim3 AGG_GRID(cdiv(NN, 8), 4);
    const dim3 EDGE_GRID(cdiv(EE, T), 4);

    // ---- CSR build ----
    zero_int<<<cdiv(4L * NN, T), T>>>(pcur, 4 * NN);
    hist_k<<<EDGE_GRID, T>>>(e0, e1, e2, e3);
    scan_k<<<4, 1024>>>();
    copy_cursor<<<cdiv(4L * NN, T), T>>>();
    fill_k<<<EDGE_GRID, T>>>(e0, e1, e2, e3);

    // ---- Layer 0 (D=128): A-buf = pA; out h -> g_h, self-cols of layer1 -> pB ----
    build_Bbf<<<cdiv(5L * 128 * 256, T), T>>>(Wl0, Wr0, bl0, 128);
    aggregate_k<4><<<AGG_GRID, 256>>>(x, pA);
    convert_self<<<cdiv((long)NN * 32, T), T>>>(x, pA);
    mma_main<<<RB, 256, MST * STB>>>(pA, 1280, pbias, ph, pB, 2560, 1024, 2304, 20);

    // ---- Layer 1 (D=256): A-buf = pB; out h -> g_h2, self of layer2 -> pA ----
    build_Bbf<<<cdiv(5L * 256 * 256, T), T>>>(Wl, Wr, bl, 256);
    aggregate_k<8><<<AGG_GRID, 256>>>(ph, pB);
    mma_main<<<RB, 256, MST * STB>>>(pB, 2560, pbias, ph2, pA, 2560, 1024, 2304, 40);

    // ---- Layer 2: A-buf = pA; out only hi/lo tail layout -> pB (stride 512) ----
    build_Bbf<<<cdiv(5L * 256 * 256, T), T>>>(Wl + (size_t)4 * 256 * 256,
                                              Wr + (size_t)4 * 256 * 256,
                                              bl + (size_t)4 * 256, 256);
    aggregate_k<8><<<AGG_GRID, 256>>>(ph2, pA);
    mma_main<<<RB, 256, MST * STB>>>(pA, 2560, pbias, nullptr, pB, 512, 0, 256, 40);

    // ---- lin: [N,256]@[256,128]+b -> fp32 g_h (ldc 128) ----
    build_W<<<cdiv(128L * 256, T), T>>>(lin_W, 256, 128);
    mma_gemm<<<TAIL_GRID, 256>>>(pB, 512, pBt, 768, lin_b, ph, 128, 128, 8, 0, nullptr, 0);

    // onset pooling + LN1 -> hl (pA, stride 256)
    pool_gather<<<cdiv(NN, 8), 256>>>(ph, pm);
    layernorm_hl<<<cdiv(NN, 8), 256>>>(pm, pA, norm_g, norm_b);

    // pW1 (relu) -> fp32 g_h2 (ldc 128)
    build_W<<<cdiv(128L * 128, T), T>>>(pW1, 128, 128);
    mma_gemm<<<TAIL_GRID, 256>>>(pA, 256, pBt, 384, pb1, ph2, 128, 128, 4, 1, nullptr, 0);
    // LN2 -> hl (pB, stride 256)
    layernorm_hl<<<cdiv(NN, 8), 256>>>(ph2, pB, pln_g, pln_b);
    // pW2 -> hl only (pA, stride 256)
    build_W<<<cdiv(128L * 128, T), T>>>(pW2, 128, 128);
    mma_gemm<<<TAIL_GRID, 256>>>(pB, 256, pBt, 384, pb2, nullptr, 128, 128, 4, 0, pA, 256);
    // cW1 (relu, Nout=64) -> fp32 g_h (ldc 64)
    build_W<<<cdiv(128L * 128, T), T>>>(cW1, 128, 64);
    mma_gemm<<<TAIL_GRID, 256>>>(pA, 256, pBt, 384, cb1, ph, 64, 64, 4, 1, nullptr, 0);

    zero_buf<<<1, 128>>>(pstats, 128);
    bn_stats<<<512, 256>>>(ph);
    finalize_k<<<cdiv(NN, 256), 256>>>(ph, bn_g, bn_b, cW2, cb2, out);
}

// round 7
// speedup vs baseline: 2.8798x; 1.2449x over previous
#include <cuda_runtime.h>
#include <cuda_fp16.h>
#include <cstdint>

#define NN 50000
#define EE 500000

// ---------------- scratch (static device globals; no runtime allocation) ----------------
__device__ __align__(16) float g_m[(size_t)NN * 128];            // pooling temp
__device__ __align__(16) __half g_AbfA[(size_t)NN * 2560];       // ping A' = [hi(5D) | lo(5D)]
__device__ __align__(16) __half g_AbfB[(size_t)NN * 2560];       // pong A'
__device__ __align__(16) __half g_Bbf[(size_t)256 * 2560];       // main B' = [Bh | Bh], K2 = 10D
__device__ __align__(16) __half g_Bt[(size_t)128 * 512];         // tail B' = [Wh | Wh]
__device__ __align__(16) float g_bias[256];
__device__ __align__(16) float g_h[(size_t)NN * 256];
__device__ __align__(16) float g_h2[(size_t)NN * 256];
__device__ __align__(16) float g_stats[128];
// CSR
__device__ int g_off[4 * (NN + 1)];
__device__ int g_list[4 * EE];
__device__ int g_cur[4 * NN];

// ---------------- helpers ----------------
__device__ __forceinline__ uint32_t smem_u32(const void* p) {
    uint32_t a;
    asm("{ .reg .u64 t; cvta.to.shared.u64 t, %1; cvt.u32.u64 %0, t; }" : "=r"(a) : "l"(p));
    return a;
}
__device__ __forceinline__ void cp_async16(uint32_t dst, const void* src, int sz) {
    asm volatile("cp.async.cg.shared.global [%0], [%1], 16, %2;"
                 :: "r"(dst), "l"(src), "r"(sz) : "memory");
}
__device__ __forceinline__ void cp_commit() { asm volatile("cp.async.commit_group;" ::: "memory"); }
template <int Nw>
__device__ __forceinline__ void cp_wait() { asm volatile("cp.async.wait_group %0;" ::"n"(Nw) : "memory"); }

__device__ __forceinline__ uint32_t pack_h2(__half a, __half b) {
    __half2 t = __halves2half2(a, b);
    return *(uint32_t*)&t;
}
// fp32 -> fp16 hi/lo pair (hi+lo represents x to ~2^-22)
__device__ __forceinline__ void hl_pack(float x, float y, uint32_t& hi, uint32_t& lo) {
    __half hx = __float2half_rn(x);
    __half hy = __float2half_rn(y);
    hi = pack_h2(hx, hy);
    lo = pack_h2(__float2half_rn(x - __half2float(hx)),
                 __float2half_rn(y - __half2float(hy)));
}
__device__ __forceinline__ void ldsm4(uint32_t& r0, uint32_t& r1, uint32_t& r2, uint32_t& r3,
                                      uint32_t addr) {
    asm volatile("ldmatrix.sync.aligned.m8n8.x4.shared.b16 {%0,%1,%2,%3}, [%4];"
                 : "=r"(r0), "=r"(r1), "=r"(r2), "=r"(r3) : "r"(addr));
}

// ---------------- CSR build ----------------
__global__ void zero_int(int* __restrict__ p, int n) {
    int i = blockIdx.x * blockDim.x + threadIdx.x;
    if (i < n) p[i] = 0;
}
__global__ void hist_k(const int* __restrict__ e0, const int* __restrict__ e1,
                       const int* __restrict__ e2, const int* __restrict__ e3) {
    int t = blockIdx.y;
    const int* e = (t == 0) ? e0 : (t == 1) ? e1 : (t == 2) ? e2 : e3;
    int i = blockIdx.x * blockDim.x + threadIdx.x;
    if (i < EE) atomicAdd(&g_cur[t * NN + e[EE + i]], 1);
}
__global__ void __launch_bounds__(1024) scan_k() {
    int t = blockIdx.x;
    const int C = (NN + 1023) / 1024;
    __shared__ int part[1024];
    int start = threadIdx.x * C;
    int s = 0;
    for (int i = 0; i < C; i++) {
        int j = start + i;
        if (j < NN) s += g_cur[t * NN + j];
    }
    part[threadIdx.x] = s;
    __syncthreads();
    if (threadIdx.x == 0) {
        int a = 0;
        for (int i = 0; i < 1024; i++) { int v = part[i]; part[i] = a; a += v; }
    }
    __syncthreads();
    int a = part[threadIdx.x];
    for (int i = 0; i < C; i++) {
        int j = start + i;
        if (j < NN) {
            g_off[t * (NN + 1) + j] = a;
            a += g_cur[t * NN + j];
        }
    }
    if (threadIdx.x == 0) g_off[t * (NN + 1) + NN] = EE;
}
__global__ void copy_cursor() {
    int i = blockIdx.x * blockDim.x + threadIdx.x;
    if (i < 4 * NN) {
        int t = i / NN, j = i - t * NN;
        g_cur[i] = g_off[t * (NN + 1) + j];
    }
}
__global__ void fill_k(const int* __restrict__ e0, const int* __restrict__ e1,
                       const int* __restrict__ e2, const int* __restrict__ e3) {
    int t = blockIdx.y;
    const int* e = (t == 0) ? e0 : (t == 1) ? e1 : (t == 2) ? e2 : e3;
    int i = blockIdx.x * blockDim.x + threadIdx.x;
    if (i < EE) {
        int d = e[EE + i];
        int p = atomicAdd(&g_cur[t * NN + d], 1);
        g_list[t * EE + p] = e[i];
    }
}

// ---------------- CSR gather-aggregate: mean -> fp16 hi/lo into A' ----------------
template <int VP>
__global__ void __launch_bounds__(256) aggregate_k(const float* __restrict__ h,
                                                   __half* __restrict__ dst) {
    const int D = 32 * VP, KA = 10 * D;
    int wid = threadIdx.x >> 5, lane = threadIdx.x & 31;
    int n = blockIdx.x * 8 + wid;
    int t = blockIdx.y;
    if (n >= NN) return;
    int beg = g_off[t * (NN + 1) + n], end = g_off[t * (NN + 1) + n + 1];
    float acc[VP];
#pragma unroll
    for (int i = 0; i < VP; i++) acc[i] = 0.f;
    const int* lst = g_list + (size_t)t * EE;
    for (int e = beg; e < end; e++) {
        int s = __ldg(&lst[e]);
        const float4* src = (const float4*)(h + (size_t)s * D + lane * VP);
#pragma unroll
        for (int q = 0; q < VP / 4; q++) {
            float4 v = __ldg(&src[q]);
            acc[q * 4 + 0] += v.x; acc[q * 4 + 1] += v.y;
            acc[q * 4 + 2] += v.z; acc[q * 4 + 3] += v.w;
        }
    }
    float inv = 1.0f / fmaxf((float)(end - beg), 1.0f);
    uint32_t hw[VP / 2], lw[VP / 2];
#pragma unroll
    for (int i = 0; i < VP / 2; i++)
        hl_pack(acc[2 * i] * inv, acc[2 * i + 1] * inv, hw[i], lw[i]);
    __half* dhi = dst + (size_t)n * KA + t * D + lane * VP;
    __half* dlo = dhi + 5 * D;
    if (VP == 8) {
        *(uint4*)dhi = make_uint4(hw[0], hw[1], hw[2], hw[3]);
        *(uint4*)dlo = make_uint4(lw[0], lw[1], lw[2], lw[3]);
    } else {
        *(uint2*)dhi = make_uint2(hw[0], hw[1]);
        *(uint2*)dlo = make_uint2(lw[0], lw[1]);
    }
}

// self part for layer 0 (input x, D=128): hi at [4D,5D), lo at [9D,10D)
__global__ void convert_self(const float* __restrict__ h, __half* __restrict__ dst) {
    const int D = 128, KA = 1280;
    long i = (long)blockIdx.x * blockDim.x + threadIdx.x;
    if (i >= (long)NN * 32) return;
    int n = (int)(i >> 5);
    int c = (int)(i & 31) * 4;
    float4 v = *(const float4*)&h[(size_t)n * D + c];
    uint32_t h0, l0, h1, l1;
    hl_pack(v.x, v.y, h0, l0);
    hl_pack(v.z, v.w, h1, l1);
    *(uint2*)(dst + (size_t)n * KA + 4 * D + c) = make_uint2(h0, h1);
    *(uint2*)(dst + (size_t)n * KA + 9 * D + c) = make_uint2(l0, l1);
}

// tail weight build: W [K, Nout] fp32 -> g_Bt[128][2K] = [Wh | Wh]
__global__ void build_W(const float* __restrict__ W, int K, int Nout) {
    long i = (long)blockIdx.x * blockDim.x + threadIdx.x;
    if (i >= (long)128 * K) return;
    int n = (int)(i / K), k = (int)(i % K);
    float v = (n < Nout) ? W[(size_t)k * Nout + n] : 0.f;
    __half hi = __float2half_rn(v);
    g_Bt[(size_t)n * 2 * K + k] = hi;
    g_Bt[(size_t)n * 2 * K + K + k] = hi;
}

// main weight build: stacked [Wl(4D); sumWr(D)] -> g_Bbf[n][10D] = [Bh | Bh]
__global__ void build_Bbf(const float* __restrict__ Wl, const float* __restrict__ Wr,
                          const float* __restrict__ bl, int D) {
    long i = (long)blockIdx.x * blockDim.x + threadIdx.x;
    long total = (long)5 * D * 256;
    if (i >= total) return;
    int k = (int)(i / 256), n = (int)(i % 256);
    float v;
    if (k < 4 * D) {
        v = Wl[(size_t)k * 256 + n];
    } else {
        int kk = k - 4 * D;
        v = Wr[(size_t)kk * 256 + n] + Wr[((size_t)D + kk) * 256 + n] +
            Wr[((size_t)2 * D + kk) * 256 + n] + Wr[((size_t)3 * D + kk) * 256 + n];
    }
    int K2 = 10 * D;
    __half hi = __float2half_rn(v);
    g_Bbf[(size_t)n * K2 + k] = hi;
    g_Bbf[(size_t)n * K2 + 5 * D + k] = hi;
    if (i < 256) g_bias[i] = bl[i] + bl[256 + i] + bl[512 + i] + bl[768 + i];
}

// ---------------- main GNN GEMM: CTA 128x256, warp 64x64, ldmatrix, 3-stage ----------------
// C = A'[M,KA] @ B'[256,KA]^T, linear chunks (A' = [hi|lo], B' = [Bh|Bh]).
#define MST 3
#define STB 30720  // stage: A 128*40*2 + B 256*40*2
__global__ void __launch_bounds__(256, 1)
mma_main(const __half* __restrict__ A, int KA,
         const float* __restrict__ bias, float* __restrict__ Cf,
         __half* __restrict__ Chl, int hlStride, int hiOff, int loOff) {
    extern __shared__ char smem[];
    const uint32_t sb = smem_u32(smem);
    const int NC = KA / 32;
    int tid = threadIdx.x;
    int wid = tid >> 5, lane = tid & 31;
    int t4 = lane >> 2, tq = lane & 3;
    int m0 = (wid & 1) * 64, n0 = (wid >> 1) * 64;
    int rowBase = blockIdx.x * 128;

    float acc[4][8][4];
#pragma unroll
    for (int i = 0; i < 4; i++)
#pragma unroll
        for (int j = 0; j < 8; j++)
#pragma unroll
            for (int q = 0; q < 4; q++) acc[i][j][q] = 0.f;

    auto issue = [&](int cc, int s) {
        uint32_t abase = sb + s * STB;
        uint32_t bbase = abase + 10240;
#pragma unroll
        for (int i = 0; i < 2; i++) {
            int u = tid + i * 256;
            int r = u >> 2, q = u & 3;
            int gr = rowBase + r;
            cp_async16(abase + r * 80 + q * 16,
                       A + (size_t)gr * KA + cc * 32 + q * 8, gr < NN ? 16 : 0);
        }
#pragma unroll
        for (int i = 0; i < 4; i++) {
            int u = tid + i * 256;
            int r = u >> 2, q = u & 3;
            cp_async16(bbase + r * 80 + q * 16,
                       g_Bbf + (size_t)r * KA + cc * 32 + q * 8, 16);
        }
        cp_commit();
    };

    uint32_t aOff = (uint32_t)((m0 + (lane & 15)) * 80 + (lane >> 4) * 16);
    uint32_t bOff = (uint32_t)((n0 + ((lane >> 4) << 3) + (lane & 7)) * 80 + ((lane >> 3) & 1) * 16);

    issue(0, 0);
    issue(1, 1);

    for (int it = 0; it < NC; it++) {
        int s = it - (it / MST) * MST;
        cp_wait<1>();
        __syncthreads();
        uint32_t abase = sb + s * STB;
        uint32_t bbase = abase + 10240;
#pragma unroll
        for (int ks = 0; ks < 2; ks++) {
            uint32_t a[4][4], b[4][4];
#pragma unroll
            for (int tm = 0; tm < 4; tm++)
                ldsm4(a[tm][0], a[tm][1], a[tm][2], a[tm][3],
                      abase + aOff + tm * 1280 + ks * 32);
#pragma unroll
            for (int tb = 0; tb < 4; tb++)
                ldsm4(b[tb][0], b[tb][1], b[tb][2], b[tb][3],
                      bbase + bOff + tb * 1280 + ks * 32);
#pragma unroll
            for (int tm = 0; tm < 4; tm++)
#pragma unroll
                for (int tn = 0; tn < 8; tn++) {
                    uint32_t b0 = b[tn >> 1][(tn & 1) * 2];
                    uint32_t b1 = b[tn >> 1][(tn & 1) * 2 + 1];
                    asm volatile(
                        "mma.sync.aligned.m16n8k16.row.col.f32.f16.f16.f32 "
                        "{%0,%1,%2,%3}, {%4,%5,%6,%7}, {%8,%9}, {%0,%1,%2,%3};"
                        : "+f"(acc[tm][tn][0]), "+f"(acc[tm][tn][1]),
                          "+f"(acc[tm][tn][2]), "+f"(acc[tm][tn][3])
                        : "r"(a[tm][0]), "r"(a[tm][1]), "r"(a[tm][2]), "r"(a[tm][3]),
                          "r"(b0), "r"(b1));
                }
        }
        __syncthreads();
        if (it + 2 < NC) issue(it + 2, (it + 2) - ((it + 2) / MST) * MST);
    }

#pragma unroll
    for (int tm = 0; tm < 4; tm++) {
        int r0 = rowBase + m0 + tm * 16 + t4;
        int r1 = r0 + 8;
#pragma unroll
        for (int tn = 0; tn < 8; tn++) {
            int col = n0 + tn * 8 + tq * 2;
            float bx = bias[col], by = bias[col + 1];
            float v0x = fmaxf(acc[tm][tn][0] + bx, 0.f);
            float v0y = fmaxf(acc[tm][tn][1] + by, 0.f);
            float v1x = fmaxf(acc[tm][tn][2] + bx, 0.f);
            float v1y = fmaxf(acc[tm][tn][3] + by, 0.f);
            if (r0 < NN) {
                if (Cf) *(float2*)&Cf[(size_t)r0 * 256 + col] = make_float2(v0x, v0y);
                uint32_t hi, lo;
                hl_pack(v0x, v0y, hi, lo);
                *(uint32_t*)(Chl + (size_t)r0 * hlStride + hiOff + col) = hi;
                *(uint32_t*)(Chl + (size_t)r0 * hlStride + loOff + col) = lo;
            }
            if (r1 < NN) {
                if (Cf) *(float2*)&Cf[(size_t)r1 * 256 + col] = make_float2(v1x, v1y);
                uint32_t hi, lo;
                hl_pack(v1x, v1y, hi, lo);
                *(uint32_t*)(Chl + (size_t)r1 * hlStride + hiOff + col) = hi;
                *(uint32_t*)(Chl + (size_t)r1 * hlStride + loOff + col) = lo;
            }
        }
    }
}

// ---------------- generic tail fp16 GEMM (CTA 128x128, warp 32x64) ----------------
__global__ void __launch_bounds__(256, 2)
mma_gemm(const __half* __restrict__ A, int KA,
         const __half* __restrict__ B, int K3,
         const float* __restrict__ bias, float* __restrict__ Cf,
         int ldc, int Nout, int relu,
         __half* __restrict__ Chl, int hlStride) {
    __shared__ __half As[2][128][40];
    __shared__ __half Bs[2][128][40];
    int tid = threadIdx.x;
    int wid = tid >> 5, lane = tid & 31;
    int t4 = lane >> 2, tq = lane & 3;
    int warp_m = wid & 3;
    int warp_n = wid >> 2;
    int rowBase = blockIdx.y * 128;
    int m0 = warp_m * 32, n0 = warp_n * 64;
    int NC = KA / 32;

    float acc[2][8][4];
#pragma unroll
    for (int i = 0; i < 2; i++)
#pragma unroll
        for (int j = 0; j < 8; j++)
#pragma unroll
            for (int q = 0; q < 4; q++) acc[i][j][q] = 0.f;

    auto issue = [&](int cc, int s) {
#pragma unroll
        for (int i = 0; i < 2; i++) {
            int u = tid + i * 256;
            int r = u >> 2, q = u & 3;
            int gr = rowBase + r;
            cp_async16(smem_u32(&As[s][r][q * 8]),
                       A + (size_t)gr * KA + cc * 32 + q * 8, gr < NN ? 16 : 0);
            cp_async16(smem_u32(&Bs[s][r][q * 8]),
                       B + (size_t)r * K3 + cc * 32 + q * 8, 16);
        }
        cp_commit();
    };

    issue(0, 0);

    for (int c = 0; c < NC; c++) {
        int s = c & 1;
        if (c + 1 < NC) {
            issue(c + 1, s ^ 1);
            cp_wait<1>();
        } else {
            cp_wait<0>();
        }
        __syncthreads();
        const __half(*as)[40] = As[s];
        const __half(*bs)[40] = Bs[s];
#pragma unroll
        for (int ks = 0; ks < 2; ks++) {
            uint32_t a[2][4], b[8][2];
#pragma unroll
            for (int im = 0; im < 2; im++) {
                int rm = m0 + im * 16 + t4;
                int kc = ks * 16 + tq * 2;
                a[im][0] = *(const uint32_t*)&as[rm][kc];
                a[im][1] = *(const uint32_t*)&as[rm + 8][kc];
                a[im][2] = *(const uint32_t*)&as[rm][kc + 8];
                a[im][3] = *(const uint32_t*)&as[rm + 8][kc + 8];
            }
#pragma unroll
            for (int in = 0; in < 8; in++) {
                int rn = n0 + in * 8 + t4;
                int kc = ks * 16 + tq * 2;
                b[in][0] = *(const uint32_t*)&bs[rn][kc];
                b[in][1] = *(const uint32_t*)&bs[rn][kc + 8];
            }
#pragma unroll
            for (int im = 0; im < 2; im++)
#pragma unroll
                for (int in = 0; in < 8; in++) {
                    asm volatile(
                        "mma.sync.aligned.m16n8k16.row.col.f32.f16.f16.f32 "
                        "{%0,%1,%2,%3}, {%4,%5,%6,%7}, {%8,%9}, {%0,%1,%2,%3};"
                        : "+f"(acc[im][in][0]), "+f"(acc[im][in][1]),
                          "+f"(acc[im][in][2]), "+f"(acc[im][in][3])
                        : "r"(a[im][0]), "r"(a[im][1]), "r"(a[im][2]), "r"(a[im][3]),
                          "r"(b[in][0]), "r"(b[in][1]));
                }
        }
        __syncthreads();
    }

#pragma unroll
    for (int im = 0; im < 2; im++) {
        int gr0 = rowBase + m0 + im * 16 + t4;
#pragma unroll
        for (int in = 0; in < 8; in++) {
            int col = n0 + in * 8 + tq * 2;
            if (col >= Nout) continue;
            float bx = bias[col], by = bias[col + 1];
            float v0x = acc[im][in][0] + bx, v0y = acc[im][in][1] + by;
            float v1x = acc[im][in][2] + bx, v1y = acc[im][in][3] + by;
            if (relu) {
                v0x = fmaxf(v0x, 0.f); v0y = fmaxf(v0y, 0.f);
                v1x = fmaxf(v1x, 0.f); v1y = fmaxf(v1y, 0.f);
            }
            if (gr0 < NN) {
                if (Cf) *(float2*)&Cf[(size_t)gr0 * ldc + col] = make_float2(v0x, v0y);
                if (Chl) {
                    uint32_t hi, lo;
                    hl_pack(v0x, v0y, hi, lo);
                    *(uint32_t*)(Chl + (size_t)gr0 * hlStride + col) = hi;
                    *(uint32_t*)(Chl + (size_t)gr0 * hlStride + (hlStride >> 1) + col) = lo;
                }
            }
            if (gr0 + 8 < NN) {
                if (Cf) *(float2*)&Cf[(size_t)(gr0 + 8) * ldc + col] = make_float2(v1x, v1y);
                if (Chl) {
                    uint32_t hi, lo;
                    hl_pack(v1x, v1y, hi, lo);
                    *(uint32_t*)(Chl + (size_t)(gr0 + 8) * hlStride + col) = hi;
                    *(uint32_t*)(Chl + (size_t)(gr0 + 8) * hlStride + (hlStride >> 1) + col) = lo;
                }
            }
        }
    }
}

// ---------------- tail kernels ----------------
__global__ void zero_buf(float* __restrict__ p, long n) {
    long i = (long)blockIdx.x * blockDim.x + threadIdx.x;
    if (i < n) p[i] = 0.0f;
}

__global__ void __launch_bounds__(256) pool_gather(const float* __restrict__ hin,
                                                   float* __restrict__ hout) {
    int wid = threadIdx.x >> 5, lane = threadIdx.x & 31;
    int n = blockIdx.x * 8 + wid;
    if (n >= NN) return;
    int beg = g_off[n], end = g_off[n + 1];
    float4 acc = *(const float4*)&hin[(size_t)n * 128 + lane * 4];
    for (int e = beg; e < end; e++) {
        int s = __ldg(&g_list[e]);
        float4 v = __ldg((const float4*)&hin[(size_t)s * 128 + lane * 4]);
        acc.x += v.x; acc.y += v.y; acc.z += v.z; acc.w += v.w;
    }
    float inv = 1.0f / fmaxf((float)(end - beg), 1.0f);
    acc.x *= inv; acc.y *= inv; acc.z *= inv; acc.w *= inv;
    *(float4*)&hout[(size_t)n * 128 + lane * 4] = acc;
}

// LayerNorm (dim 128) -> fp16 hi/lo output, row stride 256 halves
__global__ void layernorm_hl(const float* __restrict__ in, __half* __restrict__ dst,
                             const float* __restrict__ g, const float* __restrict__ b) {
    int row = blockIdx.x * 8 + (threadIdx.x >> 5);
    int lane = threadIdx.x & 31;
    if (row >= NN) return;
    float4 v = *(const float4*)&in[(size_t)row * 128 + lane * 4];
    float s = v.x + v.y + v.z + v.w;
    float q = v.x * v.x + v.y * v.y + v.z * v.z + v.w * v.w;
#pragma unroll
    for (int o = 16; o; o >>= 1) {
        s += __shfl_xor_sync(0xffffffffu, s, o);
        q += __shfl_xor_sync(0xffffffffu, q, o);
    }
    float mu = s * (1.0f / 128.0f);
    float var = q * (1.0f / 128.0f) - mu * mu;
    float r = rsqrtf(var + 1e-5f);
    float4 gg = *(const float4*)&g[lane * 4];
    float4 bb = *(const float4*)&b[lane * 4];
    float ox = (v.x - mu) * r * gg.x + bb.x;
    float oy = (v.y - mu) * r * gg.y + bb.y;
    float oz = (v.z - mu) * r * gg.z + bb.z;
    float ow = (v.w - mu) * r * gg.w + bb.w;
    uint32_t h0, l0, h1, l1;
    hl_pack(ox, oy, h0, l0);
    hl_pack(oz, ow, h1, l1);
    *(uint2*)(dst + (size_t)row * 256 + lane * 4) = make_uint2(h0, h1);
    *(uint2*)(dst + (size_t)row * 256 + 128 + lane * 4) = make_uint2(l0, l1);
}

__global__ void bn_stats(const float* __restrict__ z) {
    __shared__ float ssum[256], ssq[256];
    int c = threadIdx.x & 63;
    int sub = threadIdx.x >> 6;
    float s = 0.f, q = 0.f;
    for (long r = (long)blockIdx.x * 4 + sub; r < NN; r += (long)gridDim.x * 4) {
        float v = z[r * 64 + c];
        s += v; q += v * v;
    }
    ssum[threadIdx.x] = s; ssq[threadIdx.x] = q;
    __syncthreads();
    if (sub == 0) {
        s = ssum[c] + ssum[64 + c] + ssum[128 + c] + ssum[192 + c];
        q = ssq[c] + ssq[64 + c] + ssq[128 + c] + ssq[192 + c];
        atomicAdd(&g_stats[c], s);
        atomicAdd(&g_stats[64 + c], q);
    }
}

__global__ void finalize_k(const float* __restrict__ z, const float* __restrict__ bn_g,
                           const float* __restrict__ bn_b, const float* __restrict__ cW2,
                           const float* __restrict__ cb2, float* __restrict__ out) {
    __shared__ float w[448], smu[64], sr[64], sg[64], sb[64], sb2[7];
    int tid = threadIdx.x;
    for (int i = tid; i < 448; i += blockDim.x) w[i] = cW2[i];
    if (tid < 64) {
        float mu = g_stats[tid] / (float)NN;
        float var = g_stats[64 + tid] / (float)NN - mu * mu;
        smu[tid] = mu;
        sr[tid] = rsqrtf(var + 1e-5f);
        sg[tid] = bn_g[tid];
        sb[tid] = bn_b[tid];
    }
    if (tid < 7) sb2[tid] = cb2[tid];
    __syncthreads();
    int row = blockIdx.x * blockDim.x + tid;
    if (row >= NN) return;
    float logits[7];
#pragma unroll
    for (int j = 0; j < 7; j++) logits[j] = sb2[j];
    for (int c = 0; c < 64; c += 4) {
        float4 v4 = *(const float4*)&z[(size_t)row * 64 + c];
        float vv[4] = {v4.x, v4.y, v4.z, v4.w};
#pragma unroll
        for (int u = 0; u < 4; u++) {
            int cc = c + u;
            float v = (vv[u] - smu[cc]) * sr[cc] * sg[cc] + sb[cc];
#pragma unroll
            for (int j = 0; j < 7; j++) logits[j] += v * w[cc * 7 + j];
        }
    }
    float m = logits[0];
#pragma unroll
    for (int j = 1; j < 7; j++) m = fmaxf(m, logits[j]);
    float ssum = 0.f;
#pragma unroll
    for (int j = 0; j < 7; j++) { logits[j] = expf(logits[j] - m); ssum += logits[j]; }
    float inv = 1.0f / ssum;
#pragma unroll
    for (int j = 0; j < 7; j++) out[(size_t)row * 7 + j] = logits[j] * inv;
}

// ---------------- host launcher ----------------
static inline int cdiv(long a, int b) { return (int)((a + b - 1) / b); }

extern "C" void kernel_launch(void* const* d_in, const int* in_sizes, int n_in,
                              void* d_out, int out_size) {
    const float* x = (const float*)d_in[0];
    const int* e0 = (const int*)d_in[1];
    const int* e1 = (const int*)d_in[2];
    const int* e2 = (const int*)d_in[3];
    const int* e3 = (const int*)d_in[4];
    const float* Wl0 = (const float*)d_in[5];
    const float* bl0 = (const float*)d_in[6];
    const float* Wr0 = (const float*)d_in[7];
    const float* Wl = (const float*)d_in[8];
    const float* bl = (const float*)d_in[9];
    const float* Wr = (const float*)d_in[10];
    const float* lin_W = (const float*)d_in[11];
    const float* lin_b = (const float*)d_in[12];
    const float* norm_g = (const float*)d_in[13];
    const float* norm_b = (const float*)d_in[14];
    const float* pW1 = (const float*)d_in[15];
    const float* pb1 = (const float*)d_in[16];
    const float* pln_g = (const float*)d_in[17];
    const float* pln_b = (const float*)d_in[18];
    const float* pW2 = (const float*)d_in[19];
    const float* pb2 = (const float*)d_in[20];
    const float* cW1 = (const float*)d_in[21];
    const float* cb1 = (const float*)d_in[22];
    const float* bn_g = (const float*)d_in[23];
    const float* bn_b = (const float*)d_in[24];
    const float* cW2 = (const float*)d_in[25];
    const float* cb2 = (const float*)d_in[26];
    float* out = (float*)d_out;

    float *pm, *pbias, *ph, *ph2, *pstats;
    __half *pA, *pB, *pBt;
    int* pcur;
    cudaGetSymbolAddress((void**)&pm, g_m);
    cudaGetSymbolAddress((void**)&pA, g_AbfA);
    cudaGetSymbolAddress((void**)&pB, g_AbfB);
    cudaGetSymbolAddress((void**)&pBt, g_Bt);
    cudaGetSymbolAddress((void**)&pbias, g_bias);
    cudaGetSymbolAddress((void**)&ph, g_h);
    cudaGetSymbolAddress((void**)&ph2, g_h2);
    cudaGetSymbolAddress((void**)&pstats, g_stats);
    cudaGetSymbolAddress((void**)&pcur, g_cur);

    static bool attr_set = false;
    if (!attr_set) {
        cudaFuncSetAttribute(mma_main, cudaFuncAttributeMaxDynamicSharedMemorySize, MST * STB);
        attr_set = true;
    }

    const int T = 256;
    const int RB = cdiv(NN, 128);
    const dim3 TAIL_GRID(1, RB);
    const dim3 AGG_GRID(cdiv(NN, 8), 4);
    const dim3 EDGE_GRID(cdiv(EE, T), 4);

    // ---- CSR build ----
    zero_int<<<cdiv(4L * NN, T), T>>>(pcur, 4 * NN);
    hist_k<<<EDGE_GRID, T>>>(e0, e1, e2, e3);
    scan_k<<<4, 1024>>>();
    copy_cursor<<<cdiv(4L * NN, T), T>>>();
    fill_k<<<EDGE_GRID, T>>>(e0, e1, e2, e3);

    // ---- Layer 0 (D=128, KA=1280): out h -> g_h, self-cols of layer1 -> pB ----
    build_Bbf<<<cdiv(5L * 128 * 256, T), T>>>(Wl0, Wr0, bl0, 128);
    aggregate_k<4><<<AGG_GRID, 256>>>(x, pA);
    convert_self<<<cdiv((long)NN * 32, T), T>>>(x, pA);
    mma_main<<<RB, 256, MST * STB>>>(pA, 1280, pbias, ph, pB, 2560, 1024, 2304);

    // ---- Layer 1 (D=256, KA=2560): out h -> g_h2, self of layer2 -> pA ----
    build_Bbf<<<cdiv(5L * 256 * 256, T), T>>>(Wl, Wr, bl, 256);
    aggregate_k<8><<<AGG_GRID, 256>>>(ph, pB);
    mma_main<<<RB, 256, MST * STB>>>(pB, 2560, pbias, ph2, pA, 2560, 1024, 2304);

    // ---- Layer 2: out only hi/lo tail layout -> pB (stride 512) ----
    build_Bbf<<<cdiv(5L * 256 * 256, T), T>>>(Wl + (size_t)4 * 256 * 256,
                                              Wr + (size_t)4 * 256 * 256,
                                              bl + (size_t)4 * 256, 256);
    aggregate_k<8><<<AGG_GRID, 256>>>(ph2, pA);
    mma_main<<<RB, 256, MST * STB>>>(pA, 2560, pbias, nullptr, pB, 512, 0, 256);

    // ---- lin: [N,256]@[256,128]+b -> fp32 g_h (ldc 128) ----
    build_W<<<cdiv(128L * 256, T), T>>>(lin_W, 256, 128);
    mma_gemm<<<TAIL_GRID, 256>>>(pB, 512, pBt, 512, lin_b, ph, 128, 128, 0, nullptr, 0);

    // onset pooling + LN1 -> hl (pA, stride 256)
    pool_gather<<<cdiv(NN, 8), 256>>>(ph, pm);
    layernorm_hl<<<cdiv(NN, 8), 256>>>(pm, pA, norm_g, norm_b);

    // pW1 (relu) -> fp32 g_h2 (ldc 128)
    build_W<<<cdiv(128L * 128, T), T>>>(pW1, 128, 128);
    mma_gemm<<<TAIL_GRID, 256>>>(pA, 256, pBt, 256, pb1, ph2, 128, 128, 1, nullptr, 0);
    // LN2 -> hl (pB, stride 256)
    layernorm_hl<<<cdiv(NN, 8), 256>>>(ph2, pB, pln_g, pln_b);
    // pW2 -> hl only (pA, stride 256)
    build_W<<<cdiv(128L * 128, T), T>>>(pW2, 128, 128);
    mma_gemm<<<TAIL_GRID, 256>>>(pB, 256, pBt, 256, pb2, nullptr, 128, 128, 0, pA, 256);
    // cW1 (relu, Nout=64) -> fp32 g_h (ldc 64)
    build_W<<<cdiv(128L * 128, T), T>>>(cW1, 128, 64);
    mma_gemm<<<TAIL_GRID, 256>>>(pA, 256, pBt, 256, cb1, ph, 64, 64, 1, nullptr, 0);

    zero_buf<<<1, 128>>>(pstats, 128);
    bn_stats<<<512, 256>>>(ph);
    finalize_k<<<cdiv(NN, 256), 256>>>(ph, bn_g, bn_b, cW2, cb2, out);
}